// round 13
// baseline (speedup 1.0000x reference)
#include <cuda_runtime.h>
#include <cuda_bf16.h>
#include <cstdint>

// Problem constants: B=16, N=2048 -> NT=32768 nodes, C=H=256, E=262144, 3 layers.
#define NT   32768
#define HD   256
#define EDG  262144
#define NEG_SLOPE 0.2f
#define INV254 (1.0f / 254.0f)

// ---------------- device scratch ----------------
__device__ float  g_h[NT * HD];                // h = x @ W^T (fp32)
__device__ int8_t g_qa1[NT * HD];              // activation int8 hi digit
__device__ int8_t g_qa2[NT * HD];              // activation int8 lo digit (x254)
__device__ float  g_sa[NT];                    // activation row scales
__device__ int8_t g_qw1[3][HD * HD];           // weight int8 hi digits
__device__ int8_t g_qw2[3][HD * HD];           // weight int8 lo digits
__device__ float  g_sw[3][HD];                 // weight row scales
__device__ float  g_sp[16][NT];                // score partials: si[y*2+wn], sj[8+...]
__device__ float  g_si[NT];
__device__ float  g_sj[NT];
__device__ float  g_ex[EDG];
__device__ float  g_scale[NT];
__device__ int    g_deg[NT];
__device__ int    g_off[NT + 1];
__device__ int    g_cur[NT];
__device__ int    g_srcs[EDG];
__device__ int    g_bsum[32];
__device__ int    g_is64;

// ---------------- small helpers ----------------
__device__ __forceinline__ uint32_t smem_u32(const void* p) {
    uint32_t a;
    asm("{ .reg .u64 t; cvta.to.shared.u64 t, %1; cvt.u32.u64 %0, t; }" : "=r"(a) : "l"(p));
    return a;
}
__device__ __forceinline__ void ldsm4(uint32_t* r, uint32_t addr) {
    asm volatile("ldmatrix.sync.aligned.m8n8.x4.shared.b16 {%0,%1,%2,%3}, [%4];"
        : "=r"(r[0]), "=r"(r[1]), "=r"(r[2]), "=r"(r[3]) : "r"(addr));
}
__device__ __forceinline__ void mma_s8(int* c, const uint32_t* a, const uint32_t* b) {
    asm volatile(
        "mma.sync.aligned.m16n8k32.row.col.s32.s8.s8.s32 "
        "{%0,%1,%2,%3}, {%4,%5,%6,%7}, {%8,%9}, {%0,%1,%2,%3};"
        : "+r"(c[0]), "+r"(c[1]), "+r"(c[2]), "+r"(c[3])
        : "r"(a[0]), "r"(a[1]), "r"(a[2]), "r"(a[3]), "r"(b[0]), "r"(b[1]));
}
__device__ __forceinline__ void cpa16(uint32_t dst, const void* src) {
    asm volatile("cp.async.cg.shared.global [%0], [%1], 16;" :: "r"(dst), "l"(src));
}
// block-wide abs-max over 256 threads (8 warps); all threads must reach it
__device__ __forceinline__ float block_absmax(float v, float* red) {
    int lane = threadIdx.x & 31, wid = threadIdx.x >> 5;
    #pragma unroll
    for (int o = 16; o > 0; o >>= 1) v = fmaxf(v, __shfl_xor_sync(~0u, v, o));
    if (lane == 0) red[wid] = v;
    __syncthreads();
    if (wid == 0) {
        float t = (lane < 8) ? red[lane] : 0.f;
        #pragma unroll
        for (int o = 4; o > 0; o >>= 1) t = fmaxf(t, __shfl_xor_sync(~0u, t, o));
        if (lane == 0) red[0] = t;
    }
    __syncthreads();
    return red[0];
}
__device__ __forceinline__ void quant2(float v, float mx, int8_t& d1, int8_t& d2) {
    float inv = (mx > 0.f) ? 127.f / mx : 0.f;
    float q = v * inv;
    int a1 = __float2int_rn(q);
    int a2 = __float2int_rn((q - (float)a1) * 254.f);
    d1 = (int8_t)a1; d2 = (int8_t)a2;
}

// ---------------- edge index width ----------------
__device__ __forceinline__ int load_idx(const void* ei, int pos) {
    if (g_is64) return (int)((const long long*)ei)[pos];
    return ((const int*)ei)[pos];
}

// ---------------- init: zero degrees + detect index width (merged) ---------
__global__ void k_init(const int* ei32) {
    g_deg[blockIdx.x * 256 + threadIdx.x] = 0;
    if (blockIdx.x == 0) {
        __shared__ int any;
        if (threadIdx.x == 0) any = 0;
        __syncthreads();
        int local = 0;
        for (int i = threadIdx.x; i < 4096; i += blockDim.x) local |= ei32[2 * i + 1];
        if (local) atomicOr(&any, 1);
        __syncthreads();
        if (threadIdx.x == 0) g_is64 = (any == 0) ? 1 : 0;
    }
}

__global__ void k_hist(const void* ei) {
    int e = blockIdx.x * 256 + threadIdx.x;
    atomicAdd(&g_deg[load_idx(ei, EDG + e)], 1);
}

__global__ void k_scan1() {
    __shared__ int wsum[32];
    int tid = threadIdx.x, lane = tid & 31, w = tid >> 5;
    int i = blockIdx.x * 1024 + tid;
    int v = g_deg[i];
    int inc = v;
    #pragma unroll
    for (int o = 1; o < 32; o <<= 1) { int t = __shfl_up_sync(~0u, inc, o); if (lane >= o) inc += t; }
    if (lane == 31) wsum[w] = inc;
    __syncthreads();
    if (w == 0) {
        int s = wsum[lane], iv = s;
        #pragma unroll
        for (int o = 1; o < 32; o <<= 1) { int t = __shfl_up_sync(~0u, iv, o); if (lane >= o) iv += t; }
        wsum[lane] = iv - s;
    }
    __syncthreads();
    int val = wsum[w] + inc;
    g_off[i + 1] = val;
    if (tid == 1023) g_bsum[blockIdx.x] = val;
}

// scan3: each block redundantly computes its own base from the 32 block sums
__global__ void k_scan3() {
    __shared__ int sbase;
    int tid = threadIdx.x;
    if (tid < 32) {
        int t = (tid < (int)blockIdx.x) ? g_bsum[tid] : 0;
        #pragma unroll
        for (int o = 16; o > 0; o >>= 1) t += __shfl_xor_sync(~0u, t, o);
        if (tid == 0) sbase = t;
    }
    __syncthreads();
    int i = blockIdx.x * 1024 + tid;
    int off = g_off[i + 1] + sbase;
    g_off[i + 1] = off;
    g_cur[i] = off - g_deg[i];
    if (i == 0) g_off[0] = 0;
}

__global__ void k_scatter(const void* ei) {
    int e = blockIdx.x * 256 + threadIdx.x;
    int src = load_idx(ei, e);
    int dst = load_idx(ei, EDG + e);
    g_srcs[atomicAdd(&g_cur[dst], 1)] = src;
}

// ---------------- quantization kernels ----------------
__global__ void k_wquant(const float* __restrict__ W1,
                         const float* __restrict__ W2,
                         const float* __restrict__ W3) {
    __shared__ float red[8];
    int l = blockIdx.y, n = blockIdx.x, tid = threadIdx.x;
    const float* W = (l == 0) ? W1 : (l == 1) ? W2 : W3;
    float v = W[n * 256 + tid];
    float mx = block_absmax(fabsf(v), red);
    int8_t d1, d2;
    quant2(v, mx, d1, d2);
    g_qw1[l][n * 256 + tid] = d1;
    g_qw2[l][n * 256 + tid] = d2;
    if (tid == 0) g_sw[l][n] = mx / 127.f;
}

__global__ void k_aquant0(const float* __restrict__ x) {
    __shared__ float red[8];
    int row = blockIdx.x, tid = threadIdx.x;
    float v = x[(size_t)row * 256 + tid];
    float mx = block_absmax(fabsf(v), red);
    int8_t d1, d2;
    quant2(v, mx, d1, d2);
    g_qa1[(size_t)row * 256 + tid] = d1;
    g_qa2[(size_t)row * 256 + tid] = d2;
    if (tid == 0) g_sa[row] = mx / 127.f;
}

// ====== int8 dual-digit mma.sync GEMM: CTA 128x64, 2-stage cp.async ======
// C[m,n] = sA_m*sB_n*(HI + MID/254); HI = A1B1, MID = A1B2 + A2B1 (int32 exact).
// K=256 int8 in 4 chunks of 64B; 8 warps: 4M x 2N grid of 32x32 warp tiles.
// acc 64 regs/thread (hi+md) -> __launch_bounds__(256,2), 128-reg cap.
#define SROW   80
#define ATILE  (128 * SROW)     // 10240 B (128 rows x 64B data + 16B pad)
#define BTILE  (64 * SROW)      //  5120 B
#define OF_A1  0
#define OF_A2  ATILE
#define OF_B1  (2 * ATILE)
#define OF_B2  (2 * ATILE + BTILE)
#define BUFSZ  (2 * ATILE + 2 * BTILE)   // 30720 B per stage
#define SM_TOTAL (2 * BUFSZ)             // 61440 B dynamic

__global__ void __launch_bounds__(256, 2) k_gemm_mma(const float* __restrict__ av, int layer) {
    extern __shared__ char sm[];
    uint32_t smb = smem_u32(sm);
    int tid = threadIdx.x, lane = tid & 31, wid = tid >> 5;
    int wm = wid & 3, wn = wid >> 2;
    int m0 = blockIdx.x * 128, n0 = blockIdx.y * 64;

    const int8_t* A1 = g_qa1 + (size_t)m0 * 256;
    const int8_t* A2 = g_qa2 + (size_t)m0 * 256;
    const int8_t* B1 = g_qw1[layer] + (size_t)n0 * 256;
    const int8_t* B2 = g_qw2[layer] + (size_t)n0 * 256;

    int lrow = tid >> 2, lc4 = tid & 3;   // 64B/row chunk = 4 x 16B segments

    #define CPA_CHUNK(bb, k0)                                                 \
        { _Pragma("unroll")                                                   \
          for (int i = 0; i < 2; i++) {                                       \
              int row = lrow + i * 64;                                        \
              uint32_t so = (bb) + (uint32_t)row * SROW + lc4 * 16;           \
              size_t go = (size_t)row * 256 + (k0) + lc4 * 16;                \
              cpa16(so + OF_A1, A1 + go);                                     \
              cpa16(so + OF_A2, A2 + go);                                     \
          }                                                                   \
          {                                                                   \
              uint32_t so = (bb) + (uint32_t)lrow * SROW + lc4 * 16;          \
              size_t go = (size_t)lrow * 256 + (k0) + lc4 * 16;               \
              cpa16(so + OF_B1, B1 + go);                                     \
              cpa16(so + OF_B2, B2 + go);                                     \
          }                                                                   \
          asm volatile("cp.async.commit_group;"); }

    int quad = lane >> 3, qr = lane & 7;
    uint32_t aRel = (uint32_t)(wm * 32 + (quad & 1) * 8 + qr) * SROW
                  + (uint32_t)((quad >> 1) * 16);
    uint32_t bRel = (uint32_t)(wn * 32 + (quad >> 1) * 8 + qr) * SROW
                  + (uint32_t)((quad & 1) * 16);

    int hi[2][4][4], md[2][4][4];
    #pragma unroll
    for (int mi = 0; mi < 2; mi++)
        #pragma unroll
        for (int n8 = 0; n8 < 4; n8++)
            #pragma unroll
            for (int r = 0; r < 4; r++) { hi[mi][n8][r] = 0; md[mi][n8][r] = 0; }

    CPA_CHUNK(smb, 0);

    for (int c = 0; c < 4; c++) {
        uint32_t cur = smb + (uint32_t)(c & 1) * BUFSZ;
        if (c < 3) {
            CPA_CHUNK(smb + (uint32_t)((c + 1) & 1) * BUFSZ, (c + 1) * 64);
            asm volatile("cp.async.wait_group 1;" ::: "memory");
        } else {
            asm volatile("cp.async.wait_group 0;" ::: "memory");
        }
        __syncthreads();

        #pragma unroll
        for (int ks = 0; ks < 2; ks++) {     // k32 per step, 32B offset
            uint32_t a1f[2][4], a2f[2][4], b1f[2][4], b2f[2][4];
            #pragma unroll
            for (int mi = 0; mi < 2; mi++) {
                uint32_t ao = cur + aRel + (uint32_t)(mi * 16 * SROW + ks * 32);
                ldsm4(a1f[mi], ao + OF_A1);
                ldsm4(a2f[mi], ao + OF_A2);
            }
            #pragma unroll
            for (int nj = 0; nj < 2; nj++) {
                uint32_t bo = cur + bRel + (uint32_t)(nj * 16 * SROW + ks * 32);
                ldsm4(b1f[nj], bo + OF_B1);
                ldsm4(b2f[nj], bo + OF_B2);
            }
            #pragma unroll
            for (int mi = 0; mi < 2; mi++)
                #pragma unroll
                for (int nj = 0; nj < 2; nj++)
                    #pragma unroll
                    for (int h = 0; h < 2; h++) {
                        mma_s8(hi[mi][nj * 2 + h], a1f[mi], &b1f[nj][h * 2]);
                        mma_s8(md[mi][nj * 2 + h], a1f[mi], &b2f[nj][h * 2]);
                        mma_s8(md[mi][nj * 2 + h], a2f[mi], &b1f[nj][h * 2]);
                    }
        }
        __syncthreads();
    }

    // epilogue: dequantize, write fp32 h, fused score partials (race-free slots)
    int gid = lane >> 2, tig = lane & 3;
    int slot = blockIdx.y * 2 + wn;        // 0..7 unique per (y, wn)
    #pragma unroll
    for (int mi = 0; mi < 2; mi++) {
        int rbase = m0 + wm * 32 + mi * 16 + gid;
        float saA = g_sa[rbase], saB = g_sa[rbase + 8];
        float siA = 0.f, sjA = 0.f, siB = 0.f, sjB = 0.f;
        #pragma unroll
        for (int n8 = 0; n8 < 4; n8++) {
            int col = n0 + wn * 32 + n8 * 8 + tig * 2;
            float sb0 = g_sw[layer][col], sb1 = g_sw[layer][col + 1];
            float c0 = saA * sb0 * ((float)hi[mi][n8][0] + (float)md[mi][n8][0] * INV254);
            float c1 = saA * sb1 * ((float)hi[mi][n8][1] + (float)md[mi][n8][1] * INV254);
            float c2 = saB * sb0 * ((float)hi[mi][n8][2] + (float)md[mi][n8][2] * INV254);
            float c3 = saB * sb1 * ((float)hi[mi][n8][3] + (float)md[mi][n8][3] * INV254);
            float a0 = __ldg(av + col),       a1v = __ldg(av + col + 1);
            float b0 = __ldg(av + 256 + col), b1v = __ldg(av + 257 + col);
            siA = fmaf(c0, a0, fmaf(c1, a1v, siA));
            sjA = fmaf(c0, b0, fmaf(c1, b1v, sjA));
            siB = fmaf(c2, a0, fmaf(c3, a1v, siB));
            sjB = fmaf(c2, b0, fmaf(c3, b1v, sjB));
            float2 v0 = {c0, c1};
            float2 v1 = {c2, c3};
            *(float2*)(g_h + (size_t)rbase * 256 + col)       = v0;
            *(float2*)(g_h + (size_t)(rbase + 8) * 256 + col) = v1;
        }
        #pragma unroll
        for (int o = 1; o <= 2; o <<= 1) {
            siA += __shfl_xor_sync(~0u, siA, o);
            sjA += __shfl_xor_sync(~0u, sjA, o);
            siB += __shfl_xor_sync(~0u, siB, o);
            sjB += __shfl_xor_sync(~0u, sjB, o);
        }
        if (tig == 0) {
            g_sp[slot][rbase]         = siA;
            g_sp[8 + slot][rbase]     = sjA;
            g_sp[slot][rbase + 8]     = siB;
            g_sp[8 + slot][rbase + 8] = sjB;
        }
    }
}

// ---------------- combine score partials ----------------
__global__ void k_comb() {
    int i = blockIdx.x * 256 + threadIdx.x;
    float si = 0.f, sj = 0.f;
    #pragma unroll
    for (int s = 0; s < 8; s++) { si += g_sp[s][i]; sj += g_sp[8 + s][i]; }
    g_si[i] = si;
    g_sj[i] = sj;
}

// ---------------- segment softmax (8 lanes per dst node; deg ~ 8) ----------
__global__ void k_softmax() {
    int idx  = blockIdx.x * blockDim.x + threadIdx.x;
    int v    = idx >> 3;
    int l8   = idx & 7;
    if (v >= NT) return;
    unsigned gmask = 0xFFu << ((threadIdx.x & 31) & ~7);
    int s0 = g_off[v], s1 = g_off[v + 1];
    if (s0 == s1) { if (l8 == 0) g_scale[v] = 0.f; return; }
    float siv = g_si[v];
    float m = -1e30f;
    for (int e = s0 + l8; e < s1; e += 8) {
        float sc = siv + g_sj[g_srcs[e]];
        sc = (sc >= 0.f) ? sc : sc * NEG_SLOPE;
        g_ex[e] = sc;
        m = fmaxf(m, sc);
    }
    #pragma unroll
    for (int o = 4; o > 0; o >>= 1) m = fmaxf(m, __shfl_xor_sync(gmask, m, o));
    float sum = 0.f;
    for (int e = s0 + l8; e < s1; e += 8) {
        float ex = expf(g_ex[e] - m);
        g_ex[e] = ex;
        sum += ex;
    }
    #pragma unroll
    for (int o = 4; o > 0; o >>= 1) sum += __shfl_xor_sync(gmask, sum, o);
    if (l8 == 0) g_scale[v] = 1.f / (sum * (float)(s1 - s0));
}

// ------- aggregation + ELU; quantizes the row for the next layer ----------
__global__ void __launch_bounds__(256) k_agg(float* __restrict__ outExt, int last) {
    __shared__ float red[8];
    int v = blockIdx.x, tid = threadIdx.x;
    int s0 = g_off[v], s1 = g_off[v + 1];
    float acc = 0.f;
    int e = s0;
    for (; e + 4 <= s1; e += 4) {
        int i0 = g_srcs[e], i1 = g_srcs[e + 1], i2 = g_srcs[e + 2], i3 = g_srcs[e + 3];
        float w0 = g_ex[e], w1 = g_ex[e + 1], w2 = g_ex[e + 2], w3 = g_ex[e + 3];
        float v0 = g_h[(size_t)i0 * 256 + tid];
        float v1 = g_h[(size_t)i1 * 256 + tid];
        float v2 = g_h[(size_t)i2 * 256 + tid];
        float v3 = g_h[(size_t)i3 * 256 + tid];
        acc = fmaf(w0, v0, acc); acc = fmaf(w1, v1, acc);
        acc = fmaf(w2, v2, acc); acc = fmaf(w3, v3, acc);
    }
    for (; e < s1; e++)
        acc = fmaf(g_ex[e], g_h[(size_t)g_srcs[e] * 256 + tid], acc);
    float val = (s1 > s0) ? acc * g_scale[v] : 0.f;
    val = (val > 0.f) ? val : expm1f(val);
    if (last) {
        outExt[(size_t)v * 256 + tid] = val;
    } else {
        float mx = block_absmax(fabsf(val), red);
        int8_t d1, d2;
        quant2(val, mx, d1, d2);
        g_qa1[(size_t)v * 256 + tid] = d1;
        g_qa2[(size_t)v * 256 + tid] = d2;
        if (tid == 0) g_sa[v] = mx / 127.f;
    }
}

// ---------------- launch ----------------
extern "C" void kernel_launch(void* const* d_in, const int* in_sizes, int n_in,
                              void* d_out, int out_size) {
    const float* tf = (const float*)d_in[0];
    const void*  ei = d_in[1];
    const float* a[3] = {(const float*)d_in[3], (const float*)d_in[5], (const float*)d_in[7]};
    float* out = (float*)d_out;

    cudaFuncSetAttribute(k_gemm_mma, cudaFuncAttributeMaxDynamicSharedMemorySize, SM_TOTAL);

    // quant + init first; GEMM L0 is the 4th launch (ncu captures launch #4)
    k_wquant<<<dim3(HD, 3), 256>>>((const float*)d_in[2],
                                   (const float*)d_in[4],
                                   (const float*)d_in[6]);
    k_aquant0<<<NT, 256>>>(tf);
    k_init<<<NT / 256, 256>>>((const int*)ei);

    k_gemm_mma<<<dim3(NT / 128, 4), 256, SM_TOTAL>>>(a[0], 0);   // 4th launch

    // CSR build (completes before softmax needs it)
    k_hist<<<EDG / 256, 256>>>(ei);
    k_scan1<<<NT / 1024, 1024>>>();
    k_scan3<<<NT / 1024, 1024>>>();
    k_scatter<<<EDG / 256, 256>>>(ei);

    for (int l = 0; l < 3; l++) {
        if (l > 0) k_gemm_mma<<<dim3(NT / 128, 4), 256, SM_TOTAL>>>(a[l], l);
        k_comb<<<NT / 256, 256>>>();
        k_softmax<<<NT * 8 / 256, 256>>>();
        k_agg<<<NT, 256>>>(out, (l == 2) ? 1 : 0);
    }
}

// round 14
// speedup vs baseline: 1.3545x; 1.3545x over previous
#include <cuda_runtime.h>
#include <cuda_bf16.h>
#include <cstdint>

// Problem constants: B=16, N=2048 -> NT=32768 nodes, C=H=256, E=262144, 3 layers.
#define NT   32768
#define HD   256
#define EDG  262144
#define NEG_SLOPE 0.2f

// ---------------- device scratch ----------------
__device__ float g_h[NT * HD];                 // h = x @ W^T (fp32)
__device__ __nv_bfloat16 g_a1[NT * HD];        // activation hi split
__device__ __nv_bfloat16 g_a2[NT * HD];        // activation lo split
__device__ __nv_bfloat16 g_w1[3][HD * HD];     // weight hi splits (all layers)
__device__ __nv_bfloat16 g_w2[3][HD * HD];     // weight lo splits
__device__ float g_sp[16][NT];                 // score partials: si[y*2+wn], sj[8+...]
__device__ float g_si[NT];
__device__ float g_sj[NT];
__device__ float g_ex[EDG];
__device__ float g_scale[NT];
__device__ int   g_deg[NT];
__device__ int   g_off[NT + 1];
__device__ int   g_cur[NT];
__device__ int   g_srcs[EDG];
__device__ int   g_bsum[32];
__device__ int   g_is64;

// ---------------- small helpers ----------------
__device__ __forceinline__ uint32_t smem_u32(const void* p) {
    uint32_t a;
    asm("{ .reg .u64 t; cvta.to.shared.u64 t, %1; cvt.u32.u64 %0, t; }" : "=r"(a) : "l"(p));
    return a;
}
__device__ __forceinline__ void ldsm4(uint32_t* r, uint32_t addr) {
    asm volatile("ldmatrix.sync.aligned.m8n8.x4.shared.b16 {%0,%1,%2,%3}, [%4];"
        : "=r"(r[0]), "=r"(r[1]), "=r"(r[2]), "=r"(r[3]) : "r"(addr));
}
__device__ __forceinline__ void mma16816(float* c, const uint32_t* a, const uint32_t* b) {
    asm volatile(
        "mma.sync.aligned.m16n8k16.row.col.f32.bf16.bf16.f32 "
        "{%0,%1,%2,%3}, {%4,%5,%6,%7}, {%8,%9}, {%0,%1,%2,%3};"
        : "+f"(c[0]), "+f"(c[1]), "+f"(c[2]), "+f"(c[3])
        : "r"(a[0]), "r"(a[1]), "r"(a[2]), "r"(a[3]), "r"(b[0]), "r"(b[1]));
}
__device__ __forceinline__ void cpa16(uint32_t dst, const void* src) {
    asm volatile("cp.async.cg.shared.global [%0], [%1], 16;" :: "r"(dst), "l"(src));
}

// ---------------- edge index width ----------------
__device__ __forceinline__ int load_idx(const void* ei, int pos) {
    if (g_is64) return (int)((const long long*)ei)[pos];
    return ((const int*)ei)[pos];
}

// ---------------- init: zero degrees + detect index width (merged) ---------
__global__ void k_init(const int* ei32) {
    g_deg[blockIdx.x * 256 + threadIdx.x] = 0;
    if (blockIdx.x == 0) {
        __shared__ int any;
        if (threadIdx.x == 0) any = 0;
        __syncthreads();
        int local = 0;
        for (int i = threadIdx.x; i < 4096; i += blockDim.x) local |= ei32[2 * i + 1];
        if (local) atomicOr(&any, 1);
        __syncthreads();
        if (threadIdx.x == 0) g_is64 = (any == 0) ? 1 : 0;
    }
}

__global__ void k_hist(const void* ei) {
    int e = blockIdx.x * 256 + threadIdx.x;
    atomicAdd(&g_deg[load_idx(ei, EDG + e)], 1);
}

__global__ void k_scan1() {
    __shared__ int wsum[32];
    int tid = threadIdx.x, lane = tid & 31, w = tid >> 5;
    int i = blockIdx.x * 1024 + tid;
    int v = g_deg[i];
    int inc = v;
    #pragma unroll
    for (int o = 1; o < 32; o <<= 1) { int t = __shfl_up_sync(~0u, inc, o); if (lane >= o) inc += t; }
    if (lane == 31) wsum[w] = inc;
    __syncthreads();
    if (w == 0) {
        int s = wsum[lane], iv = s;
        #pragma unroll
        for (int o = 1; o < 32; o <<= 1) { int t = __shfl_up_sync(~0u, iv, o); if (lane >= o) iv += t; }
        wsum[lane] = iv - s;
    }
    __syncthreads();
    int val = wsum[w] + inc;
    g_off[i + 1] = val;
    if (tid == 1023) g_bsum[blockIdx.x] = val;
}

// scan3: each block redundantly computes its own base from the 32 block sums
__global__ void k_scan3() {
    __shared__ int sbase;
    int tid = threadIdx.x;
    if (tid < 32) {
        int t = (tid < (int)blockIdx.x) ? g_bsum[tid] : 0;
        #pragma unroll
        for (int o = 16; o > 0; o >>= 1) t += __shfl_xor_sync(~0u, t, o);
        if (tid == 0) sbase = t;
    }
    __syncthreads();
    int i = blockIdx.x * 1024 + tid;
    int off = g_off[i + 1] + sbase;
    g_off[i + 1] = off;
    g_cur[i] = off - g_deg[i];
    if (i == 0) g_off[0] = 0;
}

__global__ void k_scatter(const void* ei) {
    int e = blockIdx.x * 256 + threadIdx.x;
    int src = load_idx(ei, e);
    int dst = load_idx(ei, EDG + e);
    g_srcs[atomicAdd(&g_cur[dst], 1)] = src;
}

// ---------------- splits: fp32 -> bf16 hi/lo ----------------
__global__ void k_wsplit_all(const float* __restrict__ W1,
                             const float* __restrict__ W2,
                             const float* __restrict__ W3) {
    int l = blockIdx.y;
    const float* W = (l == 0) ? W1 : (l == 1) ? W2 : W3;
    int i = blockIdx.x * 256 + threadIdx.x;
    float w = W[i];
    __nv_bfloat16 hi = __float2bfloat16_rn(w);
    g_w1[l][i] = hi;
    g_w2[l][i] = __float2bfloat16_rn(w - __bfloat162float(hi));
}

__global__ void k_asplit0(const float* __restrict__ x) {
    int i = blockIdx.x * 256 + threadIdx.x;
    float4 v = ((const float4*)x)[i];
    __nv_bfloat16 hx = __float2bfloat16_rn(v.x), hy = __float2bfloat16_rn(v.y);
    __nv_bfloat16 hz = __float2bfloat16_rn(v.z), hw = __float2bfloat16_rn(v.w);
    __nv_bfloat162 h01 = {hx, hy}, h23 = {hz, hw};
    __nv_bfloat162 l01 = {__float2bfloat16_rn(v.x - __bfloat162float(hx)),
                          __float2bfloat16_rn(v.y - __bfloat162float(hy))};
    __nv_bfloat162 l23 = {__float2bfloat16_rn(v.z - __bfloat162float(hz)),
                          __float2bfloat16_rn(v.w - __bfloat162float(hw))};
    uint2 p1 = {*(uint32_t*)&h01, *(uint32_t*)&h23};
    uint2 p2 = {*(uint32_t*)&l01, *(uint32_t*)&l23};
    *(uint2*)((char*)g_a1 + (size_t)i * 8) = p1;
    *(uint2*)((char*)g_a2 + (size_t)i * 8) = p2;
}

// ====== bf16 mma.sync GEMM: CTA 128x64, K-chunk 64, 2-stage cp.async ======
// C[NT,256] = A @ W^T via 3-term split (a1*b1 + a1*b2 + a2*b1), fp32 accum.
// K=256 in 4 chunks of 64 (128 B/row): 8 barriers total vs 16.
// 8 warps: 4M x 2N grid of 32x32 warp tiles. __launch_bounds__(256,2).
#define SROW   144              // 128 B data + 16 B pad (conflict-free rows)
#define ATILE  (128 * SROW)     // 18432 B
#define BTILE  (64 * SROW)      //  9216 B
#define OF_A1  0
#define OF_A2  ATILE
#define OF_B1  (2 * ATILE)
#define OF_B2  (2 * ATILE + BTILE)
#define BUFSZ  (2 * ATILE + 2 * BTILE)   // 55296 B per stage
#define SM_TOTAL (2 * BUFSZ)             // 110592 B dynamic -> 2 CTAs/SM

__global__ void __launch_bounds__(256, 2) k_gemm_mma(const float* __restrict__ av, int layer) {
    extern __shared__ char sm[];
    uint32_t smb = smem_u32(sm);
    int tid = threadIdx.x, lane = tid & 31, wid = tid >> 5;
    int wm = wid & 3, wn = wid >> 2;
    int m0 = blockIdx.x * 128, n0 = blockIdx.y * 64;

    const __nv_bfloat16* A1 = g_a1 + (size_t)m0 * 256;
    const __nv_bfloat16* A2 = g_a2 + (size_t)m0 * 256;
    const __nv_bfloat16* B1 = g_w1[layer] + (size_t)n0 * 256;
    const __nv_bfloat16* B2 = g_w2[layer] + (size_t)n0 * 256;

    // chunk = 64 k-cols = 128 B/row = 8 x 16B segments.
    // A: 128 rows x 8 segs = 1024 segs / 256 thr = 4 per thread (per split).
    // B:  64 rows x 8 segs =  512 segs / 256 thr = 2 per thread (per split).
    int arow = tid >> 1, aseg = (tid & 1) * 4;   // A: 2 threads/row, 4 segs each
    int brow = tid >> 2, bseg = (tid & 3) * 2;   // B: 4 threads/row, 2 segs each

    #define CPA_CHUNK(bb, k0)                                                 \
        { _Pragma("unroll")                                                   \
          for (int s = 0; s < 4; s++) {                                       \
              uint32_t so = (bb) + (uint32_t)arow * SROW + (aseg + s) * 16;   \
              size_t go = (size_t)arow * 256 + (k0) + (aseg + s) * 8;         \
              cpa16(so + OF_A1, A1 + go);                                     \
              cpa16(so + OF_A2, A2 + go);                                     \
          }                                                                   \
          _Pragma("unroll")                                                   \
          for (int s = 0; s < 2; s++) {                                       \
              uint32_t so = (bb) + (uint32_t)brow * SROW + (bseg + s) * 16;   \
              size_t go = (size_t)brow * 256 + (k0) + (bseg + s) * 8;         \
              cpa16(so + OF_B1, B1 + go);                                     \
              cpa16(so + OF_B2, B2 + go);                                     \
          }                                                                   \
          asm volatile("cp.async.commit_group;"); }

    int quad = lane >> 3, qr = lane & 7;
    uint32_t aRel = (uint32_t)(wm * 32 + (quad & 1) * 8 + qr) * SROW
                  + (uint32_t)((quad >> 1) * 16);
    uint32_t bRel = (uint32_t)(wn * 32 + (quad >> 1) * 8 + qr) * SROW
                  + (uint32_t)((quad & 1) * 16);

    float acc[2][4][4];
    #pragma unroll
    for (int mi = 0; mi < 2; mi++)
        #pragma unroll
        for (int n8 = 0; n8 < 4; n8++)
            #pragma unroll
            for (int r = 0; r < 4; r++) acc[mi][n8][r] = 0.f;

    CPA_CHUNK(smb, 0);

    for (int c = 0; c < 4; c++) {
        uint32_t cur = smb + (uint32_t)(c & 1) * BUFSZ;
        if (c < 3) {
            CPA_CHUNK(smb + (uint32_t)((c + 1) & 1) * BUFSZ, (c + 1) * 64);
            asm volatile("cp.async.wait_group 1;" ::: "memory");
        } else {
            asm volatile("cp.async.wait_group 0;" ::: "memory");
        }
        __syncthreads();

        #pragma unroll
        for (int ks = 0; ks < 4; ks++) {    // k16 per step, 32 B offset
            uint32_t a1f[2][4], a2f[2][4], b1f[2][4], b2f[2][4];
            #pragma unroll
            for (int mi = 0; mi < 2; mi++) {
                uint32_t ao = cur + aRel + (uint32_t)(mi * 16 * SROW + ks * 32);
                ldsm4(a1f[mi], ao + OF_A1);
                ldsm4(a2f[mi], ao + OF_A2);
            }
            #pragma unroll
            for (int nj = 0; nj < 2; nj++) {
                uint32_t bo = cur + bRel + (uint32_t)(nj * 16 * SROW + ks * 32);
                ldsm4(b1f[nj], bo + OF_B1);
                ldsm4(b2f[nj], bo + OF_B2);
            }
            #pragma unroll
            for (int mi = 0; mi < 2; mi++)
                #pragma unroll
                for (int nj = 0; nj < 2; nj++)
                    #pragma unroll
                    for (int h = 0; h < 2; h++) {
                        float* C = acc[mi][nj * 2 + h];
                        mma16816(C, a1f[mi], &b1f[nj][h * 2]);
                        mma16816(C, a1f[mi], &b2f[nj][h * 2]);
                        mma16816(C, a2f[mi], &b1f[nj][h * 2]);
                    }
        }
        __syncthreads();   // protect cur buffer before refill at c+1
    }

    // epilogue: write fp32 h + fused score partials (race-free slots)
    int gid = lane >> 2, tig = lane & 3;
    int slot = blockIdx.y * 2 + wn;        // 0..7 unique per (y, wn)
    #pragma unroll
    for (int mi = 0; mi < 2; mi++) {
        int rbase = m0 + wm * 32 + mi * 16 + gid;
        float siA = 0.f, sjA = 0.f, siB = 0.f, sjB = 0.f;
        #pragma unroll
        for (int n8 = 0; n8 < 4; n8++) {
            int col = n0 + wn * 32 + n8 * 8 + tig * 2;
            float a0 = __ldg(av + col),       a1v = __ldg(av + col + 1);
            float b0 = __ldg(av + 256 + col), b1v = __ldg(av + 257 + col);
            float c0 = acc[mi][n8][0], c1 = acc[mi][n8][1];
            float c2 = acc[mi][n8][2], c3 = acc[mi][n8][3];
            siA = fmaf(c0, a0, fmaf(c1, a1v, siA));
            sjA = fmaf(c0, b0, fmaf(c1, b1v, sjA));
            siB = fmaf(c2, a0, fmaf(c3, a1v, siB));
            sjB = fmaf(c2, b0, fmaf(c3, b1v, sjB));
            float2 v0 = {c0, c1};
            float2 v1 = {c2, c3};
            *(float2*)(g_h + (size_t)rbase * 256 + col)       = v0;
            *(float2*)(g_h + (size_t)(rbase + 8) * 256 + col) = v1;
        }
        #pragma unroll
        for (int o = 1; o <= 2; o <<= 1) {
            siA += __shfl_xor_sync(~0u, siA, o);
            sjA += __shfl_xor_sync(~0u, sjA, o);
            siB += __shfl_xor_sync(~0u, siB, o);
            sjB += __shfl_xor_sync(~0u, sjB, o);
        }
        if (tig == 0) {
            g_sp[slot][rbase]         = siA;
            g_sp[8 + slot][rbase]     = sjA;
            g_sp[slot][rbase + 8]     = siB;
            g_sp[8 + slot][rbase + 8] = sjB;
        }
    }
}

// ---------------- combine score partials ----------------
__global__ void k_comb() {
    int i = blockIdx.x * 256 + threadIdx.x;
    float si = 0.f, sj = 0.f;
    #pragma unroll
    for (int s = 0; s < 8; s++) { si += g_sp[s][i]; sj += g_sp[8 + s][i]; }
    g_si[i] = si;
    g_sj[i] = sj;
}

// ---------------- segment softmax (8 lanes per dst node; deg ~ 8) ----------
__global__ void k_softmax() {
    int idx  = blockIdx.x * blockDim.x + threadIdx.x;
    int v    = idx >> 3;
    int l8   = idx & 7;
    if (v >= NT) return;
    unsigned gmask = 0xFFu << ((threadIdx.x & 31) & ~7);
    int s0 = g_off[v], s1 = g_off[v + 1];
    if (s0 == s1) { if (l8 == 0) g_scale[v] = 0.f; return; }
    float siv = g_si[v];
    float m = -1e30f;
    for (int e = s0 + l8; e < s1; e += 8) {
        float sc = siv + g_sj[g_srcs[e]];
        sc = (sc >= 0.f) ? sc : sc * NEG_SLOPE;
        g_ex[e] = sc;
        m = fmaxf(m, sc);
    }
    #pragma unroll
    for (int o = 4; o > 0; o >>= 1) m = fmaxf(m, __shfl_xor_sync(gmask, m, o));
    float sum = 0.f;
    for (int e = s0 + l8; e < s1; e += 8) {
        float ex = expf(g_ex[e] - m);
        g_ex[e] = ex;
        sum += ex;
    }
    #pragma unroll
    for (int o = 4; o > 0; o >>= 1) sum += __shfl_xor_sync(gmask, sum, o);
    if (l8 == 0) g_scale[v] = 1.f / (sum * (float)(s1 - s0));
}

// ---------------- aggregation + ELU; writes bf16 splits for next layer ------
__global__ void __launch_bounds__(256) k_agg(float* __restrict__ outExt, int last) {
    int v = blockIdx.x, tid = threadIdx.x;
    int s0 = g_off[v], s1 = g_off[v + 1];
    float acc = 0.f;
    int e = s0;
    for (; e + 4 <= s1; e += 4) {
        int i0 = g_srcs[e], i1 = g_srcs[e + 1], i2 = g_srcs[e + 2], i3 = g_srcs[e + 3];
        float w0 = g_ex[e], w1 = g_ex[e + 1], w2 = g_ex[e + 2], w3 = g_ex[e + 3];
        float v0 = g_h[(size_t)i0 * 256 + tid];
        float v1 = g_h[(size_t)i1 * 256 + tid];
        float v2 = g_h[(size_t)i2 * 256 + tid];
        float v3 = g_h[(size_t)i3 * 256 + tid];
        acc = fmaf(w0, v0, acc); acc = fmaf(w1, v1, acc);
        acc = fmaf(w2, v2, acc); acc = fmaf(w3, v3, acc);
    }
    for (; e < s1; e++)
        acc = fmaf(g_ex[e], g_h[(size_t)g_srcs[e] * 256 + tid], acc);
    float val = (s1 > s0) ? acc * g_scale[v] : 0.f;
    val = (val > 0.f) ? val : expm1f(val);
    if (last) {
        outExt[(size_t)v * 256 + tid] = val;
    } else {
        __nv_bfloat16 hi = __float2bfloat16_rn(val);
        g_a1[(size_t)v * 256 + tid] = hi;
        g_a2[(size_t)v * 256 + tid] = __float2bfloat16_rn(val - __bfloat162float(hi));
    }
}

// ---------------- launch ----------------
extern "C" void kernel_launch(void* const* d_in, const int* in_sizes, int n_in,
                              void* d_out, int out_size) {
    const float* tf = (const float*)d_in[0];
    const void*  ei = d_in[1];
    const float* a[3] = {(const float*)d_in[3], (const float*)d_in[5], (const float*)d_in[7]};
    float* out = (float*)d_out;

    cudaFuncSetAttribute(k_gemm_mma, cudaFuncAttributeMaxDynamicSharedMemorySize, SM_TOTAL);

    // splits + init first; GEMM L0 is the 4th launch (ncu captures launch #4)
    k_wsplit_all<<<dim3(HD * HD / 256, 3), 256>>>((const float*)d_in[2],
                                                  (const float*)d_in[4],
                                                  (const float*)d_in[6]);
    k_asplit0<<<NT * HD / 4 / 256, 256>>>(tf);
    k_init<<<NT / 256, 256>>>((const int*)ei);

    k_gemm_mma<<<dim3(NT / 128, 4), 256, SM_TOTAL>>>(a[0], 0);   // 4th launch

    // CSR build (completes before softmax needs it)
    k_hist<<<EDG / 256, 256>>>(ei);
    k_scan1<<<NT / 1024, 1024>>>();
    k_scan3<<<NT / 1024, 1024>>>();
    k_scatter<<<EDG / 256, 256>>>(ei);

    for (int l = 0; l < 3; l++) {
        if (l > 0) k_gemm_mma<<<dim3(NT / 128, 4), 256, SM_TOTAL>>>(a[l], l);
        k_comb<<<NT / 256, 256>>>();
        k_softmax<<<NT * 8 / 256, 256>>>();
        k_agg<<<NT, 256>>>(out, (l == 2) ? 1 : 0);
    }
}

// round 15
// speedup vs baseline: 1.4937x; 1.1027x over previous
#include <cuda_runtime.h>
#include <cuda_bf16.h>
#include <cstdint>

// Problem constants: B=16, N=2048 -> NT=32768 nodes, C=H=256, E=262144, 3 layers.
#define NT   32768
#define HD   256
#define EDG  262144
#define NEG_SLOPE 0.2f

// ---------------- device scratch ----------------
__device__ float g_h[NT * HD];                 // h = x @ W^T (fp32)
__device__ __nv_bfloat16 g_a1[NT * HD];        // activation hi split
__device__ __nv_bfloat16 g_a2[NT * HD];        // activation lo split
__device__ __nv_bfloat16 g_w1[3][HD * HD];     // weight hi splits (all layers)
__device__ __nv_bfloat16 g_w2[3][HD * HD];     // weight lo splits
__device__ float g_sp[16][NT];                 // score partials: si[y*2+wn], sj[8+...]
__device__ float g_si[NT];
__device__ float g_sj[NT];
__device__ float g_ex[EDG];
__device__ float g_scale[NT];
__device__ int   g_deg[NT];
__device__ int   g_off[NT + 1];
__device__ int   g_cur[NT];
__device__ int   g_srcs[EDG];
__device__ int   g_bsum[32];
__device__ int   g_is64;

// ---------------- small helpers ----------------
__device__ __forceinline__ uint32_t smem_u32(const void* p) {
    uint32_t a;
    asm("{ .reg .u64 t; cvta.to.shared.u64 t, %1; cvt.u32.u64 %0, t; }" : "=r"(a) : "l"(p));
    return a;
}
__device__ __forceinline__ void ldsm4(uint32_t* r, uint32_t addr) {
    asm volatile("ldmatrix.sync.aligned.m8n8.x4.shared.b16 {%0,%1,%2,%3}, [%4];"
        : "=r"(r[0]), "=r"(r[1]), "=r"(r[2]), "=r"(r[3]) : "r"(addr));
}
__device__ __forceinline__ void mma16816(float* c, const uint32_t* a, const uint32_t* b) {
    asm volatile(
        "mma.sync.aligned.m16n8k16.row.col.f32.bf16.bf16.f32 "
        "{%0,%1,%2,%3}, {%4,%5,%6,%7}, {%8,%9}, {%0,%1,%2,%3};"
        : "+f"(c[0]), "+f"(c[1]), "+f"(c[2]), "+f"(c[3])
        : "r"(a[0]), "r"(a[1]), "r"(a[2]), "r"(a[3]), "r"(b[0]), "r"(b[1]));
}
__device__ __forceinline__ void cpa16(uint32_t dst, const void* src) {
    asm volatile("cp.async.cg.shared.global [%0], [%1], 16;" :: "r"(dst), "l"(src));
}

// ---------------- edge index width ----------------
__device__ __forceinline__ int load_idx(const void* ei, int pos) {
    if (g_is64) return (int)((const long long*)ei)[pos];
    return ((const int*)ei)[pos];
}

// ------------- prep: weight splits + activation split + init (merged) -------
__global__ void k_prep(const float* __restrict__ W1,
                       const float* __restrict__ W2,
                       const float* __restrict__ W3,
                       const float* __restrict__ x,
                       const int*   __restrict__ ei32) {
    int b = blockIdx.x, tid = threadIdx.x;
    if (b < 768) {
        int l = b >> 8;
        const float* W = (l == 0) ? W1 : (l == 1) ? W2 : W3;
        int i = (b & 255) * 256 + tid;
        float w = W[i];
        __nv_bfloat16 hi = __float2bfloat16_rn(w);
        g_w1[l][i] = hi;
        g_w2[l][i] = __float2bfloat16_rn(w - __bfloat162float(hi));
    } else if (b < 8960) {
        int i = (b - 768) * 256 + tid;            // float4 index
        float4 v = ((const float4*)x)[i];
        __nv_bfloat16 hx = __float2bfloat16_rn(v.x), hy = __float2bfloat16_rn(v.y);
        __nv_bfloat16 hz = __float2bfloat16_rn(v.z), hw = __float2bfloat16_rn(v.w);
        __nv_bfloat162 h01 = {hx, hy}, h23 = {hz, hw};
        __nv_bfloat162 l01 = {__float2bfloat16_rn(v.x - __bfloat162float(hx)),
                              __float2bfloat16_rn(v.y - __bfloat162float(hy))};
        __nv_bfloat162 l23 = {__float2bfloat16_rn(v.z - __bfloat162float(hz)),
                              __float2bfloat16_rn(v.w - __bfloat162float(hw))};
        uint2 p1 = {*(uint32_t*)&h01, *(uint32_t*)&h23};
        uint2 p2 = {*(uint32_t*)&l01, *(uint32_t*)&l23};
        *(uint2*)((char*)g_a1 + (size_t)i * 8) = p1;
        *(uint2*)((char*)g_a2 + (size_t)i * 8) = p2;
    } else {
        int bb = b - 8960;
        g_deg[bb * 256 + tid] = 0;
        if (bb == 0) {
            __shared__ int any;
            if (tid == 0) any = 0;
            __syncthreads();
            int local = 0;
            for (int i = tid; i < 4096; i += blockDim.x) local |= ei32[2 * i + 1];
            if (local) atomicOr(&any, 1);
            __syncthreads();
            if (tid == 0) g_is64 = (any == 0) ? 1 : 0;
        }
    }
}

__global__ void k_hist(const void* ei) {
    int e = blockIdx.x * 256 + threadIdx.x;
    atomicAdd(&g_deg[load_idx(ei, EDG + e)], 1);
}

__global__ void k_scan1() {
    __shared__ int wsum[32];
    int tid = threadIdx.x, lane = tid & 31, w = tid >> 5;
    int i = blockIdx.x * 1024 + tid;
    int v = g_deg[i];
    int inc = v;
    #pragma unroll
    for (int o = 1; o < 32; o <<= 1) { int t = __shfl_up_sync(~0u, inc, o); if (lane >= o) inc += t; }
    if (lane == 31) wsum[w] = inc;
    __syncthreads();
    if (w == 0) {
        int s = wsum[lane], iv = s;
        #pragma unroll
        for (int o = 1; o < 32; o <<= 1) { int t = __shfl_up_sync(~0u, iv, o); if (lane >= o) iv += t; }
        wsum[lane] = iv - s;
    }
    __syncthreads();
    int val = wsum[w] + inc;
    g_off[i + 1] = val;
    if (tid == 1023) g_bsum[blockIdx.x] = val;
}

__global__ void k_scan3() {
    __shared__ int sbase;
    int tid = threadIdx.x;
    if (tid < 32) {
        int t = (tid < (int)blockIdx.x) ? g_bsum[tid] : 0;
        #pragma unroll
        for (int o = 16; o > 0; o >>= 1) t += __shfl_xor_sync(~0u, t, o);
        if (tid == 0) sbase = t;
    }
    __syncthreads();
    int i = blockIdx.x * 1024 + tid;
    int off = g_off[i + 1] + sbase;
    g_off[i + 1] = off;
    g_cur[i] = off - g_deg[i];
    if (i == 0) g_off[0] = 0;
}

__global__ void k_scatter(const void* ei) {
    int e = blockIdx.x * 256 + threadIdx.x;
    int src = load_idx(ei, e);
    int dst = load_idx(ei, EDG + e);
    g_srcs[atomicAdd(&g_cur[dst], 1)] = src;
}

// ====== bf16 mma.sync GEMM: CTA 128x64, K-chunk 32, 3 CTAs/SM (R12 best) ======
#define SROW   80
#define ATILE  (128 * SROW)
#define BTILE  (64 * SROW)
#define OF_A1  0
#define OF_A2  ATILE
#define OF_B1  (2 * ATILE)
#define OF_B2  (2 * ATILE + BTILE)
#define BUFSZ  (2 * ATILE + 2 * BTILE)   // 30720 B per stage
#define SM_TOTAL (2 * BUFSZ)             // 61440 B dynamic

__global__ void __launch_bounds__(256, 3) k_gemm_mma(const float* __restrict__ av, int layer) {
    extern __shared__ char sm[];
    uint32_t smb = smem_u32(sm);
    int tid = threadIdx.x, lane = tid & 31, wid = tid >> 5;
    int wm = wid & 3, wn = wid >> 2;
    int m0 = blockIdx.x * 128, n0 = blockIdx.y * 64;

    const __nv_bfloat16* A1 = g_a1 + (size_t)m0 * 256;
    const __nv_bfloat16* A2 = g_a2 + (size_t)m0 * 256;
    const __nv_bfloat16* B1 = g_w1[layer] + (size_t)n0 * 256;
    const __nv_bfloat16* B2 = g_w2[layer] + (size_t)n0 * 256;

    int lrow = tid >> 2, lc4 = tid & 3;

    #define CPA_CHUNK(bb, k0)                                                 \
        { _Pragma("unroll")                                                   \
          for (int i = 0; i < 2; i++) {                                       \
              int row = lrow + i * 64;                                        \
              uint32_t so = (bb) + (uint32_t)row * SROW + lc4 * 16;           \
              size_t go = (size_t)row * 256 + (k0) + lc4 * 8;                 \
              cpa16(so + OF_A1, A1 + go);                                     \
              cpa16(so + OF_A2, A2 + go);                                     \
          }                                                                   \
          {                                                                   \
              uint32_t so = (bb) + (uint32_t)lrow * SROW + lc4 * 16;          \
              size_t go = (size_t)lrow * 256 + (k0) + lc4 * 8;                \
              cpa16(so + OF_B1, B1 + go);                                     \
              cpa16(so + OF_B2, B2 + go);                                     \
          }                                                                   \
          asm volatile("cp.async.commit_group;"); }

    int quad = lane >> 3, qr = lane & 7;
    uint32_t aRel = (uint32_t)(wm * 32 + (quad & 1) * 8 + qr) * SROW
                  + (uint32_t)((quad >> 1) * 16);
    uint32_t bRel = (uint32_t)(wn * 32 + (quad >> 1) * 8 + qr) * SROW
                  + (uint32_t)((quad & 1) * 16);

    float acc[2][4][4];
    #pragma unroll
    for (int mi = 0; mi < 2; mi++)
        #pragma unroll
        for (int n8 = 0; n8 < 4; n8++)
            #pragma unroll
            for (int r = 0; r < 4; r++) acc[mi][n8][r] = 0.f;

    CPA_CHUNK(smb, 0);

    for (int c = 0; c < 8; c++) {
        uint32_t cur = smb + (uint32_t)(c & 1) * BUFSZ;
        if (c < 7) {
            CPA_CHUNK(smb + (uint32_t)((c + 1) & 1) * BUFSZ, (c + 1) * 32);
            asm volatile("cp.async.wait_group 1;" ::: "memory");
        } else {
            asm volatile("cp.async.wait_group 0;" ::: "memory");
        }
        __syncthreads();

        #pragma unroll
        for (int ks = 0; ks < 2; ks++) {
            uint32_t a1f[2][4], a2f[2][4], b1f[2][4], b2f[2][4];
            #pragma unroll
            for (int mi = 0; mi < 2; mi++) {
                uint32_t ao = cur + aRel + (uint32_t)(mi * 16 * SROW + ks * 32);
                ldsm4(a1f[mi], ao + OF_A1);
                ldsm4(a2f[mi], ao + OF_A2);
            }
            #pragma unroll
            for (int nj = 0; nj < 2; nj++) {
                uint32_t bo = cur + bRel + (uint32_t)(nj * 16 * SROW + ks * 32);
                ldsm4(b1f[nj], bo + OF_B1);
                ldsm4(b2f[nj], bo + OF_B2);
            }
            #pragma unroll
            for (int mi = 0; mi < 2; mi++)
                #pragma unroll
                for (int nj = 0; nj < 2; nj++)
                    #pragma unroll
                    for (int h = 0; h < 2; h++) {
                        float* C = acc[mi][nj * 2 + h];
                        mma16816(C, a1f[mi], &b1f[nj][h * 2]);
                        mma16816(C, a1f[mi], &b2f[nj][h * 2]);
                        mma16816(C, a2f[mi], &b1f[nj][h * 2]);
                    }
        }
        __syncthreads();
    }

    int gid = lane >> 2, tig = lane & 3;
    int slot = blockIdx.y * 2 + wn;
    #pragma unroll
    for (int mi = 0; mi < 2; mi++) {
        int rbase = m0 + wm * 32 + mi * 16 + gid;
        float siA = 0.f, sjA = 0.f, siB = 0.f, sjB = 0.f;
        #pragma unroll
        for (int n8 = 0; n8 < 4; n8++) {
            int col = n0 + wn * 32 + n8 * 8 + tig * 2;
            float a0 = __ldg(av + col),       a1v = __ldg(av + col + 1);
            float b0 = __ldg(av + 256 + col), b1v = __ldg(av + 257 + col);
            float c0 = acc[mi][n8][0], c1 = acc[mi][n8][1];
            float c2 = acc[mi][n8][2], c3 = acc[mi][n8][3];
            siA = fmaf(c0, a0, fmaf(c1, a1v, siA));
            sjA = fmaf(c0, b0, fmaf(c1, b1v, sjA));
            siB = fmaf(c2, a0, fmaf(c3, a1v, siB));
            sjB = fmaf(c2, b0, fmaf(c3, b1v, sjB));
            float2 v0 = {c0, c1};
            float2 v1 = {c2, c3};
            *(float2*)(g_h + (size_t)rbase * 256 + col)       = v0;
            *(float2*)(g_h + (size_t)(rbase + 8) * 256 + col) = v1;
        }
        #pragma unroll
        for (int o = 1; o <= 2; o <<= 1) {
            siA += __shfl_xor_sync(~0u, siA, o);
            sjA += __shfl_xor_sync(~0u, sjA, o);
            siB += __shfl_xor_sync(~0u, siB, o);
            sjB += __shfl_xor_sync(~0u, sjB, o);
        }
        if (tig == 0) {
            g_sp[slot][rbase]         = siA;
            g_sp[8 + slot][rbase]     = sjA;
            g_sp[slot][rbase + 8]     = siB;
            g_sp[8 + slot][rbase + 8] = sjB;
        }
    }
}

// ---------------- combine score partials ----------------
__global__ void k_comb() {
    int i = blockIdx.x * 256 + threadIdx.x;
    float si = 0.f, sj = 0.f;
    #pragma unroll
    for (int s = 0; s < 8; s++) { si += g_sp[s][i]; sj += g_sp[8 + s][i]; }
    g_si[i] = si;
    g_sj[i] = sj;
}

// ---------------- segment softmax (8 lanes per dst node; deg ~ 8) ----------
__global__ void k_softmax() {
    int idx  = blockIdx.x * blockDim.x + threadIdx.x;
    int v    = idx >> 3;
    int l8   = idx & 7;
    if (v >= NT) return;
    unsigned gmask = 0xFFu << ((threadIdx.x & 31) & ~7);
    int s0 = g_off[v], s1 = g_off[v + 1];
    if (s0 == s1) { if (l8 == 0) g_scale[v] = 0.f; return; }
    float siv = g_si[v];
    float m = -1e30f;
    for (int e = s0 + l8; e < s1; e += 8) {
        float sc = siv + g_sj[g_srcs[e]];
        sc = (sc >= 0.f) ? sc : sc * NEG_SLOPE;
        g_ex[e] = sc;
        m = fmaxf(m, sc);
    }
    #pragma unroll
    for (int o = 4; o > 0; o >>= 1) m = fmaxf(m, __shfl_xor_sync(gmask, m, o));
    float sum = 0.f;
    for (int e = s0 + l8; e < s1; e += 8) {
        float ex = expf(g_ex[e] - m);
        g_ex[e] = ex;
        sum += ex;
    }
    #pragma unroll
    for (int o = 4; o > 0; o >>= 1) sum += __shfl_xor_sync(gmask, sum, o);
    if (l8 == 0) g_scale[v] = 1.f / (sum * (float)(s1 - s0));
}

// ------- aggregation + ELU (unroll 8 + predicated tail); bf16 split out -----
__global__ void __launch_bounds__(256) k_agg(float* __restrict__ outExt, int last) {
    int v = blockIdx.x, tid = threadIdx.x;
    int s0 = g_off[v], s1 = g_off[v + 1];
    float acc = 0.f;
    int e = s0;
    for (; e + 8 <= s1; e += 8) {
        int ix[8]; float w[8], hv[8];
        #pragma unroll
        for (int j = 0; j < 8; j++) { ix[j] = g_srcs[e + j]; w[j] = g_ex[e + j]; }
        #pragma unroll
        for (int j = 0; j < 8; j++) hv[j] = g_h[(size_t)ix[j] * 256 + tid];
        #pragma unroll
        for (int j = 0; j < 8; j++) acc = fmaf(w[j], hv[j], acc);
    }
    int r = s1 - e;
    if (r > 0) {                       // predicated tail, max 7 edges, 1 round
        int ix[7]; float w[7], hv[7];
        #pragma unroll
        for (int j = 0; j < 7; j++) {
            bool p = j < r;
            ix[j] = p ? g_srcs[e + j] : 0;
            w[j]  = p ? g_ex[e + j]  : 0.f;
        }
        #pragma unroll
        for (int j = 0; j < 7; j++)
            hv[j] = (j < r) ? g_h[(size_t)ix[j] * 256 + tid] : 0.f;
        #pragma unroll
        for (int j = 0; j < 7; j++) acc = fmaf(w[j], hv[j], acc);
    }
    float val = (s1 > s0) ? acc * g_scale[v] : 0.f;
    val = (val > 0.f) ? val : expm1f(val);
    if (last) {
        outExt[(size_t)v * 256 + tid] = val;
    } else {
        __nv_bfloat16 hi = __float2bfloat16_rn(val);
        g_a1[(size_t)v * 256 + tid] = hi;
        g_a2[(size_t)v * 256 + tid] = __float2bfloat16_rn(val - __bfloat162float(hi));
    }
}

// ---------------- launch ----------------
extern "C" void kernel_launch(void* const* d_in, const int* in_sizes, int n_in,
                              void* d_out, int out_size) {
    const float* tf = (const float*)d_in[0];
    const void*  ei = d_in[1];
    const float* a[3] = {(const float*)d_in[3], (const float*)d_in[5], (const float*)d_in[7]};
    float* out = (float*)d_out;

    cudaFuncSetAttribute(k_gemm_mma, cudaFuncAttributeMaxDynamicSharedMemorySize, SM_TOTAL);

    // prep (splits + init) in 1 launch; GEMM L0 is the 4th launch for ncu
    k_prep<<<9088, 256>>>((const float*)d_in[2], (const float*)d_in[4],
                          (const float*)d_in[6], tf, (const int*)ei);
    k_hist<<<EDG / 256, 256>>>(ei);
    k_scan1<<<NT / 1024, 1024>>>();

    k_gemm_mma<<<dim3(NT / 128, 4), 256, SM_TOTAL>>>(a[0], 0);   // 4th launch

    k_scan3<<<NT / 1024, 1024>>>();
    k_scatter<<<EDG / 256, 256>>>(ei);

    for (int l = 0; l < 3; l++) {
        if (l > 0) k_gemm_mma<<<dim3(NT / 128, 4), 256, SM_TOTAL>>>(a[l], l);
        k_comb<<<NT / 256, 256>>>();
        k_softmax<<<NT * 8 / 256, 256>>>();
        k_agg<<<NT, 256>>>(out, (l == 2) ? 1 : 0);
    }
}

// round 16
// speedup vs baseline: 1.5393x; 1.0305x over previous
#include <cuda_runtime.h>
#include <cuda_bf16.h>
#include <cstdint>

// Problem constants: B=16, N=2048 -> NT=32768 nodes, C=H=256, E=262144, 3 layers.
#define NT   32768
#define HD   256
#define EDG  262144
#define NEG_SLOPE 0.2f

// ---------------- device scratch ----------------
__device__ float g_h[NT * HD];                 // h = x @ W^T (fp32)
__device__ __nv_bfloat16 g_a1[NT * HD];        // activation hi split
__device__ __nv_bfloat16 g_a2[NT * HD];        // activation lo split
__device__ __nv_bfloat16 g_w1[3][HD * HD];     // weight hi splits (all layers)
__device__ __nv_bfloat16 g_w2[3][HD * HD];     // weight lo splits
__device__ float g_sp[16][NT];                 // score partials: si[y*2+wn], sj[8+...]
__device__ float g_si[NT];
__device__ float g_sj[NT];
__device__ float g_ex[EDG];
__device__ float g_scale[NT];
__device__ int   g_deg[NT];
__device__ int   g_off[NT + 1];
__device__ int   g_cur[NT];
__device__ int   g_srcs[EDG];
__device__ int   g_bsum[32];
__device__ int   g_is64;

// ---------------- small helpers ----------------
__device__ __forceinline__ uint32_t smem_u32(const void* p) {
    uint32_t a;
    asm("{ .reg .u64 t; cvta.to.shared.u64 t, %1; cvt.u32.u64 %0, t; }" : "=r"(a) : "l"(p));
    return a;
}
__device__ __forceinline__ void ldsm4(uint32_t* r, uint32_t addr) {
    asm volatile("ldmatrix.sync.aligned.m8n8.x4.shared.b16 {%0,%1,%2,%3}, [%4];"
        : "=r"(r[0]), "=r"(r[1]), "=r"(r[2]), "=r"(r[3]) : "r"(addr));
}
__device__ __forceinline__ void mma16816(float* c, const uint32_t* a, const uint32_t* b) {
    asm volatile(
        "mma.sync.aligned.m16n8k16.row.col.f32.bf16.bf16.f32 "
        "{%0,%1,%2,%3}, {%4,%5,%6,%7}, {%8,%9}, {%0,%1,%2,%3};"
        : "+f"(c[0]), "+f"(c[1]), "+f"(c[2]), "+f"(c[3])
        : "r"(a[0]), "r"(a[1]), "r"(a[2]), "r"(a[3]), "r"(b[0]), "r"(b[1]));
}
__device__ __forceinline__ void cpa16(uint32_t dst, const void* src) {
    asm volatile("cp.async.cg.shared.global [%0], [%1], 16;" :: "r"(dst), "l"(src));
}

// ---------------- edge index width ----------------
__device__ __forceinline__ int load_idx(const void* ei, int pos) {
    if (g_is64) return (int)((const long long*)ei)[pos];
    return ((const int*)ei)[pos];
}

// ------------- prep: weight splits + activation split (merged) -------
__global__ void k_prep(const float* __restrict__ W1,
                       const float* __restrict__ W2,
                       const float* __restrict__ W3,
                       const float* __restrict__ x) {
    int b = blockIdx.x, tid = threadIdx.x;
    if (b < 768) {
        int l = b >> 8;
        const float* W = (l == 0) ? W1 : (l == 1) ? W2 : W3;
        int i = (b & 255) * 256 + tid;
        float w = W[i];
        __nv_bfloat16 hi = __float2bfloat16_rn(w);
        g_w1[l][i] = hi;
        g_w2[l][i] = __float2bfloat16_rn(w - __bfloat162float(hi));
    } else {
        int i = (b - 768) * 256 + tid;            // float4 index
        float4 v = ((const float4*)x)[i];
        __nv_bfloat16 hx = __float2bfloat16_rn(v.x), hy = __float2bfloat16_rn(v.y);
        __nv_bfloat16 hz = __float2bfloat16_rn(v.z), hw = __float2bfloat16_rn(v.w);
        __nv_bfloat162 h01 = {hx, hy}, h23 = {hz, hw};
        __nv_bfloat162 l01 = {__float2bfloat16_rn(v.x - __bfloat162float(hx)),
                              __float2bfloat16_rn(v.y - __bfloat162float(hy))};
        __nv_bfloat162 l23 = {__float2bfloat16_rn(v.z - __bfloat162float(hz)),
                              __float2bfloat16_rn(v.w - __bfloat162float(hw))};
        uint2 p1 = {*(uint32_t*)&h01, *(uint32_t*)&h23};
        uint2 p2 = {*(uint32_t*)&l01, *(uint32_t*)&l23};
        *(uint2*)((char*)g_a1 + (size_t)i * 8) = p1;
        *(uint2*)((char*)g_a2 + (size_t)i * 8) = p2;
    }
}

// ---------------- init: zero degrees + detect index width ----------------
__global__ void k_init(const int* ei32) {
    g_deg[blockIdx.x * 256 + threadIdx.x] = 0;
    if (blockIdx.x == 0) {
        __shared__ int any;
        if (threadIdx.x == 0) any = 0;
        __syncthreads();
        int local = 0;
        for (int i = threadIdx.x; i < 4096; i += blockDim.x) local |= ei32[2 * i + 1];
        if (local) atomicOr(&any, 1);
        __syncthreads();
        if (threadIdx.x == 0) g_is64 = (any == 0) ? 1 : 0;
    }
}

__global__ void k_hist(const void* ei) {
    int e = blockIdx.x * 256 + threadIdx.x;
    atomicAdd(&g_deg[load_idx(ei, EDG + e)], 1);
}

__global__ void k_scan1() {
    __shared__ int wsum[32];
    int tid = threadIdx.x, lane = tid & 31, w = tid >> 5;
    int i = blockIdx.x * 1024 + tid;
    int v = g_deg[i];
    int inc = v;
    #pragma unroll
    for (int o = 1; o < 32; o <<= 1) { int t = __shfl_up_sync(~0u, inc, o); if (lane >= o) inc += t; }
    if (lane == 31) wsum[w] = inc;
    __syncthreads();
    if (w == 0) {
        int s = wsum[lane], iv = s;
        #pragma unroll
        for (int o = 1; o < 32; o <<= 1) { int t = __shfl_up_sync(~0u, iv, o); if (lane >= o) iv += t; }
        wsum[lane] = iv - s;
    }
    __syncthreads();
    int val = wsum[w] + inc;
    g_off[i + 1] = val;
    if (tid == 1023) g_bsum[blockIdx.x] = val;
}

__global__ void k_scan3() {
    __shared__ int sbase;
    int tid = threadIdx.x;
    if (tid < 32) {
        int t = (tid < (int)blockIdx.x) ? g_bsum[tid] : 0;
        #pragma unroll
        for (int o = 16; o > 0; o >>= 1) t += __shfl_xor_sync(~0u, t, o);
        if (tid == 0) sbase = t;
    }
    __syncthreads();
    int i = blockIdx.x * 1024 + tid;
    int off = g_off[i + 1] + sbase;
    g_off[i + 1] = off;
    g_cur[i] = off - g_deg[i];
    if (i == 0) g_off[0] = 0;
}

__global__ void k_scatter(const void* ei) {
    int e = blockIdx.x * 256 + threadIdx.x;
    int src = load_idx(ei, e);
    int dst = load_idx(ei, EDG + e);
    g_srcs[atomicAdd(&g_cur[dst], 1)] = src;
}

// ====== bf16 mma.sync GEMM: CTA 128x64, K-chunk 32, 3 CTAs/SM (R12 best) ======
#define SROW   80
#define ATILE  (128 * SROW)
#define BTILE  (64 * SROW)
#define OF_A1  0
#define OF_A2  ATILE
#define OF_B1  (2 * ATILE)
#define OF_B2  (2 * ATILE + BTILE)
#define BUFSZ  (2 * ATILE + 2 * BTILE)   // 30720 B per stage
#define SM_TOTAL (2 * BUFSZ)             // 61440 B dynamic

__global__ void __launch_bounds__(256, 3) k_gemm_mma(const float* __restrict__ av, int layer) {
    extern __shared__ char sm[];
    uint32_t smb = smem_u32(sm);
    int tid = threadIdx.x, lane = tid & 31, wid = tid >> 5;
    int wm = wid & 3, wn = wid >> 2;
    int m0 = blockIdx.x * 128, n0 = blockIdx.y * 64;

    const __nv_bfloat16* A1 = g_a1 + (size_t)m0 * 256;
    const __nv_bfloat16* A2 = g_a2 + (size_t)m0 * 256;
    const __nv_bfloat16* B1 = g_w1[layer] + (size_t)n0 * 256;
    const __nv_bfloat16* B2 = g_w2[layer] + (size_t)n0 * 256;

    int lrow = tid >> 2, lc4 = tid & 3;

    #define CPA_CHUNK(bb, k0)                                                 \
        { _Pragma("unroll")                                                   \
          for (int i = 0; i < 2; i++) {                                       \
              int row = lrow + i * 64;                                        \
              uint32_t so = (bb) + (uint32_t)row * SROW + lc4 * 16;           \
              size_t go = (size_t)row * 256 + (k0) + lc4 * 8;                 \
              cpa16(so + OF_A1, A1 + go);                                     \
              cpa16(so + OF_A2, A2 + go);                                     \
          }                                                                   \
          {                                                                   \
              uint32_t so = (bb) + (uint32_t)lrow * SROW + lc4 * 16;          \
              size_t go = (size_t)lrow * 256 + (k0) + lc4 * 8;                \
              cpa16(so + OF_B1, B1 + go);                                     \
              cpa16(so + OF_B2, B2 + go);                                     \
          }                                                                   \
          asm volatile("cp.async.commit_group;"); }

    int quad = lane >> 3, qr = lane & 7;
    uint32_t aRel = (uint32_t)(wm * 32 + (quad & 1) * 8 + qr) * SROW
                  + (uint32_t)((quad >> 1) * 16);
    uint32_t bRel = (uint32_t)(wn * 32 + (quad >> 1) * 8 + qr) * SROW
                  + (uint32_t)((quad & 1) * 16);

    float acc[2][4][4];
    #pragma unroll
    for (int mi = 0; mi < 2; mi++)
        #pragma unroll
        for (int n8 = 0; n8 < 4; n8++)
            #pragma unroll
            for (int r = 0; r < 4; r++) acc[mi][n8][r] = 0.f;

    CPA_CHUNK(smb, 0);

    for (int c = 0; c < 8; c++) {
        uint32_t cur = smb + (uint32_t)(c & 1) * BUFSZ;
        if (c < 7) {
            CPA_CHUNK(smb + (uint32_t)((c + 1) & 1) * BUFSZ, (c + 1) * 32);
            asm volatile("cp.async.wait_group 1;" ::: "memory");
        } else {
            asm volatile("cp.async.wait_group 0;" ::: "memory");
        }
        __syncthreads();

        #pragma unroll
        for (int ks = 0; ks < 2; ks++) {
            uint32_t a1f[2][4], a2f[2][4], b1f[2][4], b2f[2][4];
            #pragma unroll
            for (int mi = 0; mi < 2; mi++) {
                uint32_t ao = cur + aRel + (uint32_t)(mi * 16 * SROW + ks * 32);
                ldsm4(a1f[mi], ao + OF_A1);
                ldsm4(a2f[mi], ao + OF_A2);
            }
            #pragma unroll
            for (int nj = 0; nj < 2; nj++) {
                uint32_t bo = cur + bRel + (uint32_t)(nj * 16 * SROW + ks * 32);
                ldsm4(b1f[nj], bo + OF_B1);
                ldsm4(b2f[nj], bo + OF_B2);
            }
            #pragma unroll
            for (int mi = 0; mi < 2; mi++)
                #pragma unroll
                for (int nj = 0; nj < 2; nj++)
                    #pragma unroll
                    for (int h = 0; h < 2; h++) {
                        float* C = acc[mi][nj * 2 + h];
                        mma16816(C, a1f[mi], &b1f[nj][h * 2]);
                        mma16816(C, a1f[mi], &b2f[nj][h * 2]);
                        mma16816(C, a2f[mi], &b1f[nj][h * 2]);
                    }
        }
        __syncthreads();
    }

    int gid = lane >> 2, tig = lane & 3;
    int slot = blockIdx.y * 2 + wn;
    #pragma unroll
    for (int mi = 0; mi < 2; mi++) {
        int rbase = m0 + wm * 32 + mi * 16 + gid;
        float siA = 0.f, sjA = 0.f, siB = 0.f, sjB = 0.f;
        #pragma unroll
        for (int n8 = 0; n8 < 4; n8++) {
            int col = n0 + wn * 32 + n8 * 8 + tig * 2;
            float a0 = __ldg(av + col),       a1v = __ldg(av + col + 1);
            float b0 = __ldg(av + 256 + col), b1v = __ldg(av + 257 + col);
            float c0 = acc[mi][n8][0], c1 = acc[mi][n8][1];
            float c2 = acc[mi][n8][2], c3 = acc[mi][n8][3];
            siA = fmaf(c0, a0, fmaf(c1, a1v, siA));
            sjA = fmaf(c0, b0, fmaf(c1, b1v, sjA));
            siB = fmaf(c2, a0, fmaf(c3, a1v, siB));
            sjB = fmaf(c2, b0, fmaf(c3, b1v, sjB));
            float2 v0 = {c0, c1};
            float2 v1 = {c2, c3};
            *(float2*)(g_h + (size_t)rbase * 256 + col)       = v0;
            *(float2*)(g_h + (size_t)(rbase + 8) * 256 + col) = v1;
        }
        #pragma unroll
        for (int o = 1; o <= 2; o <<= 1) {
            siA += __shfl_xor_sync(~0u, siA, o);
            sjA += __shfl_xor_sync(~0u, sjA, o);
            siB += __shfl_xor_sync(~0u, siB, o);
            sjB += __shfl_xor_sync(~0u, sjB, o);
        }
        if (tig == 0) {
            g_sp[slot][rbase]         = siA;
            g_sp[8 + slot][rbase]     = sjA;
            g_sp[slot][rbase + 8]     = siB;
            g_sp[8 + slot][rbase + 8] = sjB;
        }
    }
}

// ---------------- combine score partials ----------------
__global__ void k_comb() {
    int i = blockIdx.x * 256 + threadIdx.x;
    float si = 0.f, sj = 0.f;
    #pragma unroll
    for (int s = 0; s < 8; s++) { si += g_sp[s][i]; sj += g_sp[8 + s][i]; }
    g_si[i] = si;
    g_sj[i] = sj;
}

// ---------------- segment softmax (8 lanes per dst node; deg ~ 8) ----------
__global__ void k_softmax() {
    int idx  = blockIdx.x * blockDim.x + threadIdx.x;
    int v    = idx >> 3;
    int l8   = idx & 7;
    if (v >= NT) return;
    unsigned gmask = 0xFFu << ((threadIdx.x & 31) & ~7);
    int s0 = g_off[v], s1 = g_off[v + 1];
    if (s0 == s1) { if (l8 == 0) g_scale[v] = 0.f; return; }
    float siv = g_si[v];
    float m = -1e30f;
    for (int e = s0 + l8; e < s1; e += 8) {
        float sc = siv + g_sj[g_srcs[e]];
        sc = (sc >= 0.f) ? sc : sc * NEG_SLOPE;
        g_ex[e] = sc;
        m = fmaxf(m, sc);
    }
    #pragma unroll
    for (int o = 4; o > 0; o >>= 1) m = fmaxf(m, __shfl_xor_sync(gmask, m, o));
    float sum = 0.f;
    for (int e = s0 + l8; e < s1; e += 8) {
        float ex = expf(g_ex[e] - m);
        g_ex[e] = ex;
        sum += ex;
    }
    #pragma unroll
    for (int o = 4; o > 0; o >>= 1) sum += __shfl_xor_sync(gmask, sum, o);
    if (l8 == 0) g_scale[v] = 1.f / (sum * (float)(s1 - s0));
}

// ------- aggregation + ELU (unroll 8 + predicated tail); bf16 split out -----
__global__ void __launch_bounds__(256) k_agg(float* __restrict__ outExt, int last) {
    int v = blockIdx.x, tid = threadIdx.x;
    int s0 = g_off[v], s1 = g_off[v + 1];
    float acc = 0.f;
    int e = s0;
    for (; e + 8 <= s1; e += 8) {
        int ix[8]; float w[8], hv[8];
        #pragma unroll
        for (int j = 0; j < 8; j++) { ix[j] = g_srcs[e + j]; w[j] = g_ex[e + j]; }
        #pragma unroll
        for (int j = 0; j < 8; j++) hv[j] = g_h[(size_t)ix[j] * 256 + tid];
        #pragma unroll
        for (int j = 0; j < 8; j++) acc = fmaf(w[j], hv[j], acc);
    }
    int r = s1 - e;
    if (r > 0) {                       // predicated tail, max 7 edges, 1 round
        int ix[7]; float w[7], hv[7];
        #pragma unroll
        for (int j = 0; j < 7; j++) {
            bool p = j < r;
            ix[j] = p ? g_srcs[e + j] : 0;
            w[j]  = p ? g_ex[e + j]  : 0.f;
        }
        #pragma unroll
        for (int j = 0; j < 7; j++)
            hv[j] = (j < r) ? g_h[(size_t)ix[j] * 256 + tid] : 0.f;
        #pragma unroll
        for (int j = 0; j < 7; j++) acc = fmaf(w[j], hv[j], acc);
    }
    float val = (s1 > s0) ? acc * g_scale[v] : 0.f;
    val = (val > 0.f) ? val : expm1f(val);
    if (last) {
        outExt[(size_t)v * 256 + tid] = val;
    } else {
        __nv_bfloat16 hi = __float2bfloat16_rn(val);
        g_a1[(size_t)v * 256 + tid] = hi;
        g_a2[(size_t)v * 256 + tid] = __float2bfloat16_rn(val - __bfloat162float(hi));
    }
}

// ---------------- launch ----------------
extern "C" void kernel_launch(void* const* d_in, const int* in_sizes, int n_in,
                              void* d_out, int out_size) {
    const float* tf = (const float*)d_in[0];
    const void*  ei = d_in[1];
    const float* a[3] = {(const float*)d_in[3], (const float*)d_in[5], (const float*)d_in[7]};
    float* out = (float*)d_out;

    cudaFuncSetAttribute(k_gemm_mma, cudaFuncAttributeMaxDynamicSharedMemorySize, SM_TOTAL);

    // persistent side stream + events (created once; identical captured work per call)
    static cudaStream_t s2 = nullptr;
    static cudaEvent_t ev_fork = nullptr, ev_csr = nullptr;
    if (!s2) {
        cudaStreamCreateWithFlags(&s2, cudaStreamNonBlocking);
        cudaEventCreateWithFlags(&ev_fork, cudaEventDisableTiming);
        cudaEventCreateWithFlags(&ev_csr, cudaEventDisableTiming);
    }

    // fork: CSR build on s2 runs concurrently with splits + GEMM L0 + comb
    cudaEventRecord(ev_fork, 0);
    cudaStreamWaitEvent(s2, ev_fork, 0);

    k_prep<<<8960, 256>>>((const float*)d_in[2], (const float*)d_in[4],
                          (const float*)d_in[6], tf);                 // launch 1 (s0)
    k_init<<<NT / 256, 256, 0, s2>>>((const int*)ei);                 // launch 2 (s2)
    k_hist<<<EDG / 256, 256, 0, s2>>>(ei);                            // launch 3 (s2)
    k_gemm_mma<<<dim3(NT / 128, 4), 256, SM_TOTAL>>>(a[0], 0);        // launch 4 (s0)
    k_scan1<<<NT / 1024, 1024, 0, s2>>>();
    k_scan3<<<NT / 1024, 1024, 0, s2>>>();
    k_scatter<<<EDG / 256, 256, 0, s2>>>(ei);
    cudaEventRecord(ev_csr, s2);

    k_comb<<<NT / 256, 256>>>();
    cudaStreamWaitEvent(0, ev_csr, 0);   // join: softmax needs CSR + comb

    for (int l = 0; l < 3; l++) {
        if (l > 0) {
            k_gemm_mma<<<dim3(NT / 128, 4), 256, SM_TOTAL>>>(a[l], l);
            k_comb<<<NT / 256, 256>>>();
        }
        k_softmax<<<NT * 8 / 256, 256>>>();
        k_agg<<<NT, 256>>>(out, (l == 2) ? 1 : 0);
    }
}

// round 17
// speedup vs baseline: 1.5495x; 1.0066x over previous
#include <cuda_runtime.h>
#include <cuda_bf16.h>
#include <cstdint>

// Problem constants: B=16, N=2048 -> NT=32768 nodes, C=H=256, E=262144, 3 layers.
#define NT   32768
#define HD   256
#define EDG  262144
#define NEG_SLOPE 0.2f

// ---------------- device scratch ----------------
__device__ float g_h[NT * HD];                 // h = x @ W^T (fp32)
__device__ __nv_bfloat16 g_a1[NT * HD];        // activation hi split
__device__ __nv_bfloat16 g_a2[NT * HD];        // activation lo split
__device__ __nv_bfloat16 g_w1[3][HD * HD];     // weight hi splits (all layers)
__device__ __nv_bfloat16 g_w2[3][HD * HD];     // weight lo splits
__device__ float g_sp[16][NT];                 // score partials: si[y*2+wn], sj[8+...]
__device__ float g_si[NT];
__device__ float g_sj[NT];
__device__ float g_ex[EDG];
__device__ float g_scale[NT];
__device__ int   g_deg[NT];
__device__ int   g_off[NT + 1];
__device__ int   g_cur[NT];
__device__ int   g_srcs[EDG];
__device__ int   g_bsum[32];
__device__ int   g_is64;

// ---------------- small helpers ----------------
__device__ __forceinline__ uint32_t smem_u32(const void* p) {
    uint32_t a;
    asm("{ .reg .u64 t; cvta.to.shared.u64 t, %1; cvt.u32.u64 %0, t; }" : "=r"(a) : "l"(p));
    return a;
}
__device__ __forceinline__ void ldsm4(uint32_t* r, uint32_t addr) {
    asm volatile("ldmatrix.sync.aligned.m8n8.x4.shared.b16 {%0,%1,%2,%3}, [%4];"
        : "=r"(r[0]), "=r"(r[1]), "=r"(r[2]), "=r"(r[3]) : "r"(addr));
}
__device__ __forceinline__ void mma16816(float* c, const uint32_t* a, const uint32_t* b) {
    asm volatile(
        "mma.sync.aligned.m16n8k16.row.col.f32.bf16.bf16.f32 "
        "{%0,%1,%2,%3}, {%4,%5,%6,%7}, {%8,%9}, {%0,%1,%2,%3};"
        : "+f"(c[0]), "+f"(c[1]), "+f"(c[2]), "+f"(c[3])
        : "r"(a[0]), "r"(a[1]), "r"(a[2]), "r"(a[3]), "r"(b[0]), "r"(b[1]));
}
__device__ __forceinline__ void cpa16(uint32_t dst, const void* src) {
    asm volatile("cp.async.cg.shared.global [%0], [%1], 16;" :: "r"(dst), "l"(src));
}

// ---------------- edge index width ----------------
__device__ __forceinline__ int load_idx(const void* ei, int pos) {
    if (g_is64) return (int)((const long long*)ei)[pos];
    return ((const int*)ei)[pos];
}

// ------------- prep: weight splits + activation split (merged) -------
__global__ void k_prep(const float* __restrict__ W1,
                       const float* __restrict__ W2,
                       const float* __restrict__ W3,
                       const float* __restrict__ x) {
    int b = blockIdx.x, tid = threadIdx.x;
    if (b < 768) {
        int l = b >> 8;
        const float* W = (l == 0) ? W1 : (l == 1) ? W2 : W3;
        int i = (b & 255) * 256 + tid;
        float w = W[i];
        __nv_bfloat16 hi = __float2bfloat16_rn(w);
        g_w1[l][i] = hi;
        g_w2[l][i] = __float2bfloat16_rn(w - __bfloat162float(hi));
    } else {
        int i = (b - 768) * 256 + tid;            // float4 index
        float4 v = ((const float4*)x)[i];
        __nv_bfloat16 hx = __float2bfloat16_rn(v.x), hy = __float2bfloat16_rn(v.y);
        __nv_bfloat16 hz = __float2bfloat16_rn(v.z), hw = __float2bfloat16_rn(v.w);
        __nv_bfloat162 h01 = {hx, hy}, h23 = {hz, hw};
        __nv_bfloat162 l01 = {__float2bfloat16_rn(v.x - __bfloat162float(hx)),
                              __float2bfloat16_rn(v.y - __bfloat162float(hy))};
        __nv_bfloat162 l23 = {__float2bfloat16_rn(v.z - __bfloat162float(hz)),
                              __float2bfloat16_rn(v.w - __bfloat162float(hw))};
        uint2 p1 = {*(uint32_t*)&h01, *(uint32_t*)&h23};
        uint2 p2 = {*(uint32_t*)&l01, *(uint32_t*)&l23};
        *(uint2*)((char*)g_a1 + (size_t)i * 8) = p1;
        *(uint2*)((char*)g_a2 + (size_t)i * 8) = p2;
    }
}

// ---------------- init: zero degrees + detect index width ----------------
__global__ void k_init(const int* ei32) {
    g_deg[blockIdx.x * 256 + threadIdx.x] = 0;
    if (blockIdx.x == 0) {
        __shared__ int any;
        if (threadIdx.x == 0) any = 0;
        __syncthreads();
        int local = 0;
        for (int i = threadIdx.x; i < 4096; i += blockDim.x) local |= ei32[2 * i + 1];
        if (local) atomicOr(&any, 1);
        __syncthreads();
        if (threadIdx.x == 0) g_is64 = (any == 0) ? 1 : 0;
    }
}

__global__ void k_hist(const void* ei) {
    int e = blockIdx.x * 256 + threadIdx.x;
    atomicAdd(&g_deg[load_idx(ei, EDG + e)], 1);
}

__global__ void k_scan1() {
    __shared__ int wsum[32];
    int tid = threadIdx.x, lane = tid & 31, w = tid >> 5;
    int i = blockIdx.x * 1024 + tid;
    int v = g_deg[i];
    int inc = v;
    #pragma unroll
    for (int o = 1; o < 32; o <<= 1) { int t = __shfl_up_sync(~0u, inc, o); if (lane >= o) inc += t; }
    if (lane == 31) wsum[w] = inc;
    __syncthreads();
    if (w == 0) {
        int s = wsum[lane], iv = s;
        #pragma unroll
        for (int o = 1; o < 32; o <<= 1) { int t = __shfl_up_sync(~0u, iv, o); if (lane >= o) iv += t; }
        wsum[lane] = iv - s;
    }
    __syncthreads();
    int val = wsum[w] + inc;
    g_off[i + 1] = val;
    if (tid == 1023) g_bsum[blockIdx.x] = val;
}

__global__ void k_scan3() {
    __shared__ int sbase;
    int tid = threadIdx.x;
    if (tid < 32) {
        int t = (tid < (int)blockIdx.x) ? g_bsum[tid] : 0;
        #pragma unroll
        for (int o = 16; o > 0; o >>= 1) t += __shfl_xor_sync(~0u, t, o);
        if (tid == 0) sbase = t;
    }
    __syncthreads();
    int i = blockIdx.x * 1024 + tid;
    int off = g_off[i + 1] + sbase;
    g_off[i + 1] = off;
    g_cur[i] = off - g_deg[i];
    if (i == 0) g_off[0] = 0;
}

__global__ void k_scatter(const void* ei) {
    int e = blockIdx.x * 256 + threadIdx.x;
    int src = load_idx(ei, e);
    int dst = load_idx(ei, EDG + e);
    g_srcs[atomicAdd(&g_cur[dst], 1)] = src;
}

// ====== bf16 mma.sync GEMM: CTA 128x64, K-chunk 32, 3 CTAs/SM ======
// mt0 = m-tile offset (for half-grid pipelined launches).
#define SROW   80
#define ATILE  (128 * SROW)
#define BTILE  (64 * SROW)
#define OF_A1  0
#define OF_A2  ATILE
#define OF_B1  (2 * ATILE)
#define OF_B2  (2 * ATILE + BTILE)
#define BUFSZ  (2 * ATILE + 2 * BTILE)   // 30720 B per stage
#define SM_TOTAL (2 * BUFSZ)             // 61440 B dynamic

__global__ void __launch_bounds__(256, 3) k_gemm_mma(const float* __restrict__ av,
                                                     int layer, int mt0) {
    extern __shared__ char sm[];
    uint32_t smb = smem_u32(sm);
    int tid = threadIdx.x, lane = tid & 31, wid = tid >> 5;
    int wm = wid & 3, wn = wid >> 2;
    int m0 = (mt0 + blockIdx.x) * 128, n0 = blockIdx.y * 64;

    const __nv_bfloat16* A1 = g_a1 + (size_t)m0 * 256;
    const __nv_bfloat16* A2 = g_a2 + (size_t)m0 * 256;
    const __nv_bfloat16* B1 = g_w1[layer] + (size_t)n0 * 256;
    const __nv_bfloat16* B2 = g_w2[layer] + (size_t)n0 * 256;

    int lrow = tid >> 2, lc4 = tid & 3;

    #define CPA_CHUNK(bb, k0)                                                 \
        { _Pragma("unroll")                                                   \
          for (int i = 0; i < 2; i++) {                                       \
              int row = lrow + i * 64;                                        \
              uint32_t so = (bb) + (uint32_t)row * SROW + lc4 * 16;           \
              size_t go = (size_t)row * 256 + (k0) + lc4 * 8;                 \
              cpa16(so + OF_A1, A1 + go);                                     \
              cpa16(so + OF_A2, A2 + go);                                     \
          }                                                                   \
          {                                                                   \
              uint32_t so = (bb) + (uint32_t)lrow * SROW + lc4 * 16;          \
              size_t go = (size_t)lrow * 256 + (k0) + lc4 * 8;                \
              cpa16(so + OF_B1, B1 + go);                                     \
              cpa16(so + OF_B2, B2 + go);                                     \
          }                                                                   \
          asm volatile("cp.async.commit_group;"); }

    int quad = lane >> 3, qr = lane & 7;
    uint32_t aRel = (uint32_t)(wm * 32 + (quad & 1) * 8 + qr) * SROW
                  + (uint32_t)((quad >> 1) * 16);
    uint32_t bRel = (uint32_t)(wn * 32 + (quad >> 1) * 8 + qr) * SROW
                  + (uint32_t)((quad & 1) * 16);

    float acc[2][4][4];
    #pragma unroll
    for (int mi = 0; mi < 2; mi++)
        #pragma unroll
        for (int n8 = 0; n8 < 4; n8++)
            #pragma unroll
            for (int r = 0; r < 4; r++) acc[mi][n8][r] = 0.f;

    CPA_CHUNK(smb, 0);

    for (int c = 0; c < 8; c++) {
        uint32_t cur = smb + (uint32_t)(c & 1) * BUFSZ;
        if (c < 7) {
            CPA_CHUNK(smb + (uint32_t)((c + 1) & 1) * BUFSZ, (c + 1) * 32);
            asm volatile("cp.async.wait_group 1;" ::: "memory");
        } else {
            asm volatile("cp.async.wait_group 0;" ::: "memory");
        }
        __syncthreads();

        #pragma unroll
        for (int ks = 0; ks < 2; ks++) {
            uint32_t a1f[2][4], a2f[2][4], b1f[2][4], b2f[2][4];
            #pragma unroll
            for (int mi = 0; mi < 2; mi++) {
                uint32_t ao = cur + aRel + (uint32_t)(mi * 16 * SROW + ks * 32);
                ldsm4(a1f[mi], ao + OF_A1);
                ldsm4(a2f[mi], ao + OF_A2);
            }
            #pragma unroll
            for (int nj = 0; nj < 2; nj++) {
                uint32_t bo = cur + bRel + (uint32_t)(nj * 16 * SROW + ks * 32);
                ldsm4(b1f[nj], bo + OF_B1);
                ldsm4(b2f[nj], bo + OF_B2);
            }
            #pragma unroll
            for (int mi = 0; mi < 2; mi++)
                #pragma unroll
                for (int nj = 0; nj < 2; nj++)
                    #pragma unroll
                    for (int h = 0; h < 2; h++) {
                        float* C = acc[mi][nj * 2 + h];
                        mma16816(C, a1f[mi], &b1f[nj][h * 2]);
                        mma16816(C, a1f[mi], &b2f[nj][h * 2]);
                        mma16816(C, a2f[mi], &b1f[nj][h * 2]);
                    }
        }
        __syncthreads();
    }

    int gid = lane >> 2, tig = lane & 3;
    int slot = blockIdx.y * 2 + wn;
    #pragma unroll
    for (int mi = 0; mi < 2; mi++) {
        int rbase = m0 + wm * 32 + mi * 16 + gid;
        float siA = 0.f, sjA = 0.f, siB = 0.f, sjB = 0.f;
        #pragma unroll
        for (int n8 = 0; n8 < 4; n8++) {
            int col = n0 + wn * 32 + n8 * 8 + tig * 2;
            float a0 = __ldg(av + col),       a1v = __ldg(av + col + 1);
            float b0 = __ldg(av + 256 + col), b1v = __ldg(av + 257 + col);
            float c0 = acc[mi][n8][0], c1 = acc[mi][n8][1];
            float c2 = acc[mi][n8][2], c3 = acc[mi][n8][3];
            siA = fmaf(c0, a0, fmaf(c1, a1v, siA));
            sjA = fmaf(c0, b0, fmaf(c1, b1v, sjA));
            siB = fmaf(c2, a0, fmaf(c3, a1v, siB));
            sjB = fmaf(c2, b0, fmaf(c3, b1v, sjB));
            float2 v0 = {c0, c1};
            float2 v1 = {c2, c3};
            *(float2*)(g_h + (size_t)rbase * 256 + col)       = v0;
            *(float2*)(g_h + (size_t)(rbase + 8) * 256 + col) = v1;
        }
        #pragma unroll
        for (int o = 1; o <= 2; o <<= 1) {
            siA += __shfl_xor_sync(~0u, siA, o);
            sjA += __shfl_xor_sync(~0u, sjA, o);
            siB += __shfl_xor_sync(~0u, siB, o);
            sjB += __shfl_xor_sync(~0u, sjB, o);
        }
        if (tig == 0) {
            g_sp[slot][rbase]         = siA;
            g_sp[8 + slot][rbase]     = sjA;
            g_sp[slot][rbase + 8]     = siB;
            g_sp[8 + slot][rbase + 8] = sjB;
        }
    }
}

// ---------------- combine score partials ----------------
__global__ void k_comb() {
    int i = blockIdx.x * 256 + threadIdx.x;
    float si = 0.f, sj = 0.f;
    #pragma unroll
    for (int s = 0; s < 8; s++) { si += g_sp[s][i]; sj += g_sp[8 + s][i]; }
    g_si[i] = si;
    g_sj[i] = sj;
}

// ---------------- segment softmax (8 lanes per dst node; deg ~ 8) ----------
__global__ void k_softmax(int vbase) {
    int idx  = blockIdx.x * blockDim.x + threadIdx.x;
    int v    = vbase + (idx >> 3);
    int l8   = idx & 7;
    unsigned gmask = 0xFFu << ((threadIdx.x & 31) & ~7);
    int s0 = g_off[v], s1 = g_off[v + 1];
    if (s0 == s1) { if (l8 == 0) g_scale[v] = 0.f; return; }
    float siv = g_si[v];
    float m = -1e30f;
    for (int e = s0 + l8; e < s1; e += 8) {
        float sc = siv + g_sj[g_srcs[e]];
        sc = (sc >= 0.f) ? sc : sc * NEG_SLOPE;
        g_ex[e] = sc;
        m = fmaxf(m, sc);
    }
    #pragma unroll
    for (int o = 4; o > 0; o >>= 1) m = fmaxf(m, __shfl_xor_sync(gmask, m, o));
    float sum = 0.f;
    for (int e = s0 + l8; e < s1; e += 8) {
        float ex = expf(g_ex[e] - m);
        g_ex[e] = ex;
        sum += ex;
    }
    #pragma unroll
    for (int o = 4; o > 0; o >>= 1) sum += __shfl_xor_sync(gmask, sum, o);
    if (l8 == 0) g_scale[v] = 1.f / (sum * (float)(s1 - s0));
}

// ------- aggregation + ELU (unroll 8 + predicated tail); bf16 split out -----
__global__ void __launch_bounds__(256) k_agg(float* __restrict__ outExt, int last, int vbase) {
    int v = vbase + blockIdx.x, tid = threadIdx.x;
    int s0 = g_off[v], s1 = g_off[v + 1];
    float acc = 0.f;
    int e = s0;
    for (; e + 8 <= s1; e += 8) {
        int ix[8]; float w[8], hv[8];
        #pragma unroll
        for (int j = 0; j < 8; j++) { ix[j] = g_srcs[e + j]; w[j] = g_ex[e + j]; }
        #pragma unroll
        for (int j = 0; j < 8; j++) hv[j] = g_h[(size_t)ix[j] * 256 + tid];
        #pragma unroll
        for (int j = 0; j < 8; j++) acc = fmaf(w[j], hv[j], acc);
    }
    int r = s1 - e;
    if (r > 0) {
        int ix[7]; float w[7], hv[7];
        #pragma unroll
        for (int j = 0; j < 7; j++) {
            bool p = j < r;
            ix[j] = p ? g_srcs[e + j] : 0;
            w[j]  = p ? g_ex[e + j]  : 0.f;
        }
        #pragma unroll
        for (int j = 0; j < 7; j++)
            hv[j] = (j < r) ? g_h[(size_t)ix[j] * 256 + tid] : 0.f;
        #pragma unroll
        for (int j = 0; j < 7; j++) acc = fmaf(w[j], hv[j], acc);
    }
    float val = (s1 > s0) ? acc * g_scale[v] : 0.f;
    val = (val > 0.f) ? val : expm1f(val);
    if (last) {
        outExt[(size_t)v * 256 + tid] = val;
    } else {
        __nv_bfloat16 hi = __float2bfloat16_rn(val);
        g_a1[(size_t)v * 256 + tid] = hi;
        g_a2[(size_t)v * 256 + tid] = __float2bfloat16_rn(val - __bfloat162float(hi));
    }
}

// ---------------- launch ----------------
#define HNT (NT / 2)
extern "C" void kernel_launch(void* const* d_in, const int* in_sizes, int n_in,
                              void* d_out, int out_size) {
    const float* tf = (const float*)d_in[0];
    const void*  ei = d_in[1];
    const float* a[3] = {(const float*)d_in[3], (const float*)d_in[5], (const float*)d_in[7]};
    float* out = (float*)d_out;

    cudaFuncSetAttribute(k_gemm_mma, cudaFuncAttributeMaxDynamicSharedMemorySize, SM_TOTAL);

    // persistent side stream + events (created once; identical captured work per call)
    static cudaStream_t s2 = nullptr;
    static cudaEvent_t ev[9] = {};
    if (!s2) {
        cudaStreamCreateWithFlags(&s2, cudaStreamNonBlocking);
        for (int i = 0; i < 9; i++) cudaEventCreateWithFlags(&ev[i], cudaEventDisableTiming);
    }
    // ev[0]=fork, ev[1]=csr, ev[2]=comb0, ev[3]=g1, ev[4]=comb1,
    // ev[5]=g2, ev[6]=comb2, ev[7]=end(s2), ev[8]=spare

    cudaEventRecord(ev[0], 0);
    cudaStreamWaitEvent(s2, ev[0], 0);

    k_prep<<<8960, 256>>>((const float*)d_in[2], (const float*)d_in[4],
                          (const float*)d_in[6], tf);                 // 1 (s0)
    k_init<<<NT / 256, 256, 0, s2>>>((const int*)ei);                 // 2 (s2)
    k_hist<<<EDG / 256, 256, 0, s2>>>(ei);                            // 3 (s2)
    k_gemm_mma<<<dim3(NT / 128, 4), 256, SM_TOTAL>>>(a[0], 0, 0);     // 4 (s0), full L0
    k_scan1<<<NT / 1024, 1024, 0, s2>>>();
    k_scan3<<<NT / 1024, 1024, 0, s2>>>();
    k_scatter<<<EDG / 256, 256, 0, s2>>>(ei);
    cudaEventRecord(ev[1], s2);

    k_comb<<<NT / 256, 256>>>();                                      // comb0 (s0)
    cudaStreamWaitEvent(0, ev[1], 0);     // s0: softmax needs CSR
    cudaEventRecord(ev[2], 0);            // comb0 + CSR done
    cudaStreamWaitEvent(s2, ev[2], 0);

    for (int l = 0; l < 3; l++) {
        int last = (l == 2) ? 1 : 0;
        // two independent half-chains: softmax -> agg -> gemm(l+1) per half
        k_softmax<<<HNT * 8 / 256, 256>>>(0);
        k_softmax<<<HNT * 8 / 256, 256, 0, s2>>>(HNT);
        k_agg<<<HNT, 256>>>(out, last, 0);
        k_agg<<<HNT, 256, 0, s2>>>(out, last, HNT);
        if (l < 2) {
            k_gemm_mma<<<dim3(128, 4), 256, SM_TOTAL>>>(a[l + 1], l + 1, 0);
            k_gemm_mma<<<dim3(128, 4), 256, SM_TOTAL, s2>>>(a[l + 1], l + 1, 128);
            cudaEventRecord(ev[3 + 2 * l], s2);          // gemm half1 done
            cudaStreamWaitEvent(0, ev[3 + 2 * l], 0);
            k_comb<<<NT / 256, 256>>>();
            cudaEventRecord(ev[4 + 2 * l], 0);           // comb done
            cudaStreamWaitEvent(s2, ev[4 + 2 * l], 0);
        }
    }
    // join s2 back into origin stream before capture ends
    cudaEventRecord(ev[7], s2);
    cudaStreamWaitEvent(0, ev[7], 0);
}